// round 5
// baseline (speedup 1.0000x reference)
#include <cuda_runtime.h>
#include <math.h>
#include <stdint.h>

#define B_DIM 32
#define T_DIM 2048
#define H_DIM 1024

// ---------------------------------------------------------------------------
// Scratch (allocation-free rule: __device__ globals)
// ---------------------------------------------------------------------------
__device__ float g_qproj[B_DIM * H_DIM];
__device__ float g_score[B_DIM * T_DIM];
__device__ float g_ctx_part[B_DIM * 8 * H_DIM];

// ---------------------------------------------------------------------------
// PTX helpers (sm_80-compatible; tcgen05 is NOT available at compute_103)
// ---------------------------------------------------------------------------
__device__ __forceinline__ uint32_t smem_u32(const void* p) {
    uint32_t a;
    asm("{ .reg .u64 t; cvta.to.shared.u64 t, %1; cvt.u32.u64 %0, t; }" : "=r"(a) : "l"(p));
    return a;
}
__device__ __forceinline__ void cp_async16(uint32_t dst, const void* src) {
    asm volatile("cp.async.cg.shared.global [%0], [%1], 16;" :: "r"(dst), "l"(src));
}
__device__ __forceinline__ void cp_commit() {
    asm volatile("cp.async.commit_group;" ::: "memory");
}
template <int N>
__device__ __forceinline__ void cp_wait() {
    asm volatile("cp.async.wait_group %0;" :: "n"(N) : "memory");
}
__device__ __forceinline__ void ldsm_x4(uint32_t r[4], uint32_t addr) {
    asm volatile("ldmatrix.sync.aligned.m8n8.x4.shared.b16 {%0,%1,%2,%3}, [%4];"
                 : "=r"(r[0]), "=r"(r[1]), "=r"(r[2]), "=r"(r[3]) : "r"(addr));
}
__device__ __forceinline__ void mma_tf32(float c[4], const uint32_t a[4], const uint32_t b[2]) {
    asm volatile(
        "mma.sync.aligned.m16n8k8.row.col.f32.tf32.tf32.f32 "
        "{%0,%1,%2,%3}, {%4,%5,%6,%7}, {%8,%9}, {%0,%1,%2,%3};"
        : "+f"(c[0]), "+f"(c[1]), "+f"(c[2]), "+f"(c[3])
        : "r"(a[0]), "r"(a[1]), "r"(a[2]), "r"(a[3]), "r"(b[0]), "r"(b[1]));
}
__device__ __forceinline__ float fast_tanh(float x) {
    float e = __expf(2.0f * x);
    return 1.0f - 2.0f / (e + 1.0f);
}

// ---------------------------------------------------------------------------
// Kernel 1: q_proj[b][o] = dot(query[b,:], Wq[o,:]) + bq[o]   (fp32 exact)
// ---------------------------------------------------------------------------
__global__ void qproj_kernel(const float* __restrict__ query,
                             const float* __restrict__ Wq,
                             const float* __restrict__ bq) {
    __shared__ float q_s[H_DIM];
    const int b = blockIdx.x;
    const int tid = threadIdx.x;
    for (int i = tid; i < H_DIM; i += 256) q_s[i] = query[b * H_DIM + i];
    __syncthreads();
    const int warp = tid >> 5, lane = tid & 31;
    for (int o = warp; o < H_DIM; o += 8) {
        const float* wrow = Wq + (size_t)o * H_DIM;
        float s = 0.f;
        #pragma unroll 8
        for (int h = lane; h < H_DIM; h += 32) s += q_s[h] * wrow[h];
        #pragma unroll
        for (int m = 16; m > 0; m >>= 1) s += __shfl_xor_sync(0xffffffffu, s, m);
        if (lane == 0) g_qproj[b * H_DIM + o] = s + bq[o];
    }
}

// ---------------------------------------------------------------------------
// Kernel 2: fused score GEMM, tf32 mma.sync + ldmatrix.
//   score[r] = Vb + sum_o Vw[o]*tanh(qproj[b][o]+bv[o] + sum_k V[r][k]*Wv[o][k])
// Block tile 128(M) x 256(N), 4 N-passes. 256 threads = 8 warps (2m x 4n),
// warp tile 64x64. BK=32, 2-stage cp.async pipeline.
// ---------------------------------------------------------------------------
#define BK       32
#define LDP      36                            // padded row stride (floats)
#define ST_A     (128 * LDP)                   // 4608 floats
#define ST_B     (256 * LDP)                   // 9216 floats
#define OFF_A    0
#define OFF_B    (2 * ST_A)
#define OFF_QB   (2 * ST_A + 2 * ST_B)
#define OFF_VW   (OFF_QB + 256)
#define OFF_SC   (OFF_VW + 256)
#define SMEM_FLT (OFF_SC + 128)
#define SMEM_BYTES (SMEM_FLT * 4)
#define NPASS    4
#define BN       256

__device__ __forceinline__ void load_tile_a(float* dst, const float* __restrict__ src,
                                            int k0, int tid) {
    #pragma unroll
    for (int it = 0; it < 4; ++it) {           // 128 rows x 8 chunks
        int idx = it * 256 + tid;
        int row = idx >> 3, ch = idx & 7;
        cp_async16(smem_u32(dst + row * LDP + ch * 4),
                   src + (size_t)row * H_DIM + k0 + ch * 4);
    }
}
__device__ __forceinline__ void load_tile_b(float* dst, const float* __restrict__ src,
                                            int k0, int tid) {
    #pragma unroll
    for (int it = 0; it < 8; ++it) {           // 256 rows x 8 chunks
        int idx = it * 256 + tid;
        int row = idx >> 3, ch = idx & 7;
        cp_async16(smem_u32(dst + row * LDP + ch * 4),
                   src + (size_t)row * H_DIM + k0 + ch * 4);
    }
}

__global__ void __launch_bounds__(256, 1) score_kernel(
    const float* __restrict__ values,
    const float* __restrict__ Wv,
    const float* __restrict__ bv,
    const float* __restrict__ Vw,
    const float* __restrict__ Vb) {

    extern __shared__ __align__(16) float smem[];
    float* As = smem + OFF_A;            // [2][128][36]
    float* Bs = smem + OFF_B;            // [2][256][36]
    float* qb_s = smem + OFF_QB;
    float* vw_s = smem + OFF_VW;
    float* score_s = smem + OFF_SC;

    const int tid = threadIdx.x;
    const int wid = tid >> 5, lane = tid & 31;
    const int warp_m = wid >> 2, warp_n = wid & 3;   // 2 x 4
    const int gid = lane >> 2, tig = lane & 3;
    const int l8 = lane & 7, sel = lane >> 3;

    const int r0 = blockIdx.x * 128;
    const int b  = r0 / T_DIM;
    const float* qp = g_qproj + b * H_DIM;
    const float* vrow0 = values + (size_t)r0 * H_DIM;

    if (tid < 128) score_s[tid] = 0.f;

    // ldmatrix lane addressing (same fragment mapping as validated in R4)
    const int a_row = warp_m * 64 + ((sel & 1) ? 8 : 0) + l8;
    const int a_kof = (sel & 2) ? 4 : 0;
    const int b_row = warp_n * 64 + ((sel & 2) ? 8 : 0) + l8;
    const int b_kof = (sel & 1) ? 4 : 0;

    float sacc[8];
    #pragma unroll
    for (int i = 0; i < 8; ++i) sacc[i] = 0.f;

    for (int pass = 0; pass < NPASS; ++pass) {
        const int ob = pass * BN;
        __syncthreads();                 // prev pass fully done (incl. epilogue reads)
        qb_s[tid] = qp[ob + tid] + bv[ob + tid];
        vw_s[tid] = Vw[ob + tid];

        float c[4][8][4];
        #pragma unroll
        for (int mt = 0; mt < 4; ++mt)
            #pragma unroll
            for (int nt = 0; nt < 8; ++nt)
                #pragma unroll
                for (int i = 0; i < 4; ++i) c[mt][nt][i] = 0.f;

        load_tile_a(As, vrow0, 0, tid);
        load_tile_b(Bs, Wv + (size_t)ob * H_DIM, 0, tid);
        cp_commit();

        for (int kt = 0; kt < H_DIM / BK; ++kt) {
            const int cur = kt & 1;
            if (kt + 1 < H_DIM / BK) {
                const int nxt = cur ^ 1;
                load_tile_a(As + nxt * ST_A, vrow0, (kt + 1) * BK, tid);
                load_tile_b(Bs + nxt * ST_B, Wv + (size_t)ob * H_DIM, (kt + 1) * BK, tid);
                cp_commit();
                cp_wait<1>();
            } else {
                cp_wait<0>();
            }
            __syncthreads();

            const uint32_t a_base = smem_u32(As + cur * ST_A + a_row * LDP + a_kof);
            const uint32_t b_base = smem_u32(Bs + cur * ST_B + b_row * LDP + b_kof);

            #pragma unroll
            for (int ks = 0; ks < 4; ++ks) {
                const uint32_t koff = ks * 32;   // 8 floats
                uint32_t af[4][4], bf[8][2];
                #pragma unroll
                for (int mt = 0; mt < 4; ++mt)
                    ldsm_x4(af[mt], a_base + mt * (16 * LDP * 4) + koff);
                #pragma unroll
                for (int np = 0; np < 4; ++np) {
                    uint32_t r[4];
                    ldsm_x4(r, b_base + np * (16 * LDP * 4) + koff);
                    bf[np * 2 + 0][0] = r[0];
                    bf[np * 2 + 0][1] = r[1];
                    bf[np * 2 + 1][0] = r[2];
                    bf[np * 2 + 1][1] = r[3];
                }
                #pragma unroll
                for (int mt = 0; mt < 4; ++mt)
                    #pragma unroll
                    for (int nt = 0; nt < 8; ++nt)
                        mma_tf32(c[mt][nt], af[mt], bf[nt]);
            }
            __syncthreads();
        }

        // Epilogue: tanh + Vw contraction into per-lane row partials
        #pragma unroll
        for (int nt = 0; nt < 8; ++nt) {
            const int col0 = warp_n * 64 + nt * 8 + 2 * tig;
            const float vw0 = vw_s[col0],     qb0 = qb_s[col0];
            const float vw1 = vw_s[col0 + 1], qb1 = qb_s[col0 + 1];
            #pragma unroll
            for (int mt = 0; mt < 4; ++mt) {
                sacc[mt * 2 + 0] += vw0 * fast_tanh(c[mt][nt][0] + qb0)
                                  + vw1 * fast_tanh(c[mt][nt][1] + qb1);
                sacc[mt * 2 + 1] += vw0 * fast_tanh(c[mt][nt][2] + qb0)
                                  + vw1 * fast_tanh(c[mt][nt][3] + qb1);
            }
        }
    }

    // reduce over the 4 tig lanes, then combine the 4 n-warps via smem atomics
    #pragma unroll
    for (int i = 0; i < 8; ++i) {
        sacc[i] += __shfl_xor_sync(0xffffffffu, sacc[i], 1);
        sacc[i] += __shfl_xor_sync(0xffffffffu, sacc[i], 2);
    }
    if (tig == 0) {
        #pragma unroll
        for (int i = 0; i < 8; ++i) {
            const int row = warp_m * 64 + (i >> 1) * 16 + gid + (i & 1) * 8;
            atomicAdd(&score_s[row], sacc[i]);
        }
    }
    __syncthreads();
    if (tid < 128) g_score[r0 + tid] = score_s[tid] + Vb[0];
}

// ---------------------------------------------------------------------------
// Kernel 3: softmax over T per batch. Writes weights into d_out[B*H ..].
// ---------------------------------------------------------------------------
__global__ void softmax_kernel(float* __restrict__ d_out) {
    __shared__ float red[1024];
    const int b = blockIdx.x;
    const int tid = threadIdx.x;
    const float s0 = g_score[b * T_DIM + tid];
    const float s1 = g_score[b * T_DIM + 1024 + tid];
    red[tid] = fmaxf(s0, s1);
    __syncthreads();
    for (int s = 512; s > 0; s >>= 1) {
        if (tid < s) red[tid] = fmaxf(red[tid], red[tid + s]);
        __syncthreads();
    }
    const float mx = red[0];
    __syncthreads();
    const float e0 = expf(s0 - mx), e1 = expf(s1 - mx);
    red[tid] = e0 + e1;
    __syncthreads();
    for (int s = 512; s > 0; s >>= 1) {
        if (tid < s) red[tid] += red[tid + s];
        __syncthreads();
    }
    const float inv = 1.f / red[0];
    float* w = d_out + B_DIM * H_DIM + b * T_DIM;
    w[tid] = e0 * inv;
    w[tid + 1024] = e1 * inv;
}

// ---------------------------------------------------------------------------
// Kernel 4a: context partials over T chunks; 4b: deterministic reduce.
// ---------------------------------------------------------------------------
__global__ void __launch_bounds__(1024) ctx_partial_kernel(
    const float* __restrict__ values, const float* __restrict__ d_out_w) {
    __shared__ float w_s[256];
    const int ts = blockIdx.x, b = blockIdx.y;
    const int h = threadIdx.x;
    const float* w = d_out_w + b * T_DIM + ts * 256;
    if (h < 256) w_s[h] = w[h];
    __syncthreads();
    const float* vp = values + ((size_t)b * T_DIM + ts * 256) * H_DIM + h;
    float a0 = 0.f, a1 = 0.f, a2 = 0.f, a3 = 0.f;
    #pragma unroll 8
    for (int t = 0; t < 256; t += 4) {
        a0 += w_s[t + 0] * vp[(size_t)(t + 0) * H_DIM];
        a1 += w_s[t + 1] * vp[(size_t)(t + 1) * H_DIM];
        a2 += w_s[t + 2] * vp[(size_t)(t + 2) * H_DIM];
        a3 += w_s[t + 3] * vp[(size_t)(t + 3) * H_DIM];
    }
    g_ctx_part[(b * 8 + ts) * H_DIM + h] = (a0 + a1) + (a2 + a3);
}

__global__ void __launch_bounds__(1024) ctx_reduce_kernel(float* __restrict__ d_out) {
    const int b = blockIdx.x, h = threadIdx.x;
    float s = 0.f;
    #pragma unroll
    for (int ts = 0; ts < 8; ++ts) s += g_ctx_part[(b * 8 + ts) * H_DIM + h];
    d_out[b * H_DIM + h] = s;
}

// ---------------------------------------------------------------------------
extern "C" void kernel_launch(void* const* d_in, const int* in_sizes, int n_in,
                              void* d_out, int out_size) {
    const float* query  = (const float*)d_in[0];
    const float* values = (const float*)d_in[1];
    const float* Wq     = (const float*)d_in[2];
    const float* bq     = (const float*)d_in[3];
    const float* Wv     = (const float*)d_in[4];
    const float* bv     = (const float*)d_in[5];
    const float* Vw     = (const float*)d_in[6];
    const float* Vb     = (const float*)d_in[7];
    float* out = (float*)d_out;

    cudaFuncSetAttribute(score_kernel, cudaFuncAttributeMaxDynamicSharedMemorySize,
                         SMEM_BYTES);

    qproj_kernel<<<B_DIM, 256>>>(query, Wq, bq);
    score_kernel<<<(B_DIM * T_DIM) / 128, 256, SMEM_BYTES>>>(values, Wv, bv, Vw, Vb);
    softmax_kernel<<<B_DIM, 1024>>>(out);
    ctx_partial_kernel<<<dim3(8, B_DIM), 1024>>>(values, out + B_DIM * H_DIM);
    ctx_reduce_kernel<<<B_DIM, 1024>>>(out);
}

// round 6
// speedup vs baseline: 1.0481x; 1.0481x over previous
#include <cuda_runtime.h>
#include <math.h>
#include <stdint.h>

#define B_DIM 32
#define T_DIM 2048
#define H_DIM 1024

// ---------------------------------------------------------------------------
// Scratch (allocation-free rule: __device__ globals)
// ---------------------------------------------------------------------------
__device__ float g_qproj[B_DIM * H_DIM];
__device__ float g_score[B_DIM * T_DIM];
__device__ float g_ctx_part[B_DIM * 8 * H_DIM];

// ---------------------------------------------------------------------------
// PTX helpers (sm_80-compatible; tcgen05 is NOT available at compute_103)
// ---------------------------------------------------------------------------
__device__ __forceinline__ uint32_t smem_u32(const void* p) {
    uint32_t a;
    asm("{ .reg .u64 t; cvta.to.shared.u64 t, %1; cvt.u32.u64 %0, t; }" : "=r"(a) : "l"(p));
    return a;
}
__device__ __forceinline__ void cp_async16(uint32_t dst, const void* src) {
    asm volatile("cp.async.cg.shared.global [%0], [%1], 16;" :: "r"(dst), "l"(src));
}
__device__ __forceinline__ void cp_commit() {
    asm volatile("cp.async.commit_group;" ::: "memory");
}
template <int N>
__device__ __forceinline__ void cp_wait() {
    asm volatile("cp.async.wait_group %0;" :: "n"(N) : "memory");
}
__device__ __forceinline__ void ldsm_x4(uint32_t r[4], uint32_t addr) {
    asm volatile("ldmatrix.sync.aligned.m8n8.x4.shared.b16 {%0,%1,%2,%3}, [%4];"
                 : "=r"(r[0]), "=r"(r[1]), "=r"(r[2]), "=r"(r[3]) : "r"(addr));
}
__device__ __forceinline__ void mma_tf32(float c[4], const uint32_t a[4], const uint32_t b[2]) {
    asm volatile(
        "mma.sync.aligned.m16n8k8.row.col.f32.tf32.tf32.f32 "
        "{%0,%1,%2,%3}, {%4,%5,%6,%7}, {%8,%9}, {%0,%1,%2,%3};"
        : "+f"(c[0]), "+f"(c[1]), "+f"(c[2]), "+f"(c[3])
        : "r"(a[0]), "r"(a[1]), "r"(a[2]), "r"(a[3]), "r"(b[0]), "r"(b[1]));
}
__device__ __forceinline__ float fast_tanh(float x) {
    float e = __expf(2.0f * x);
    return 1.0f - 2.0f / (e + 1.0f);
}

// ---------------------------------------------------------------------------
// Kernel 1: q_proj[b][o] = dot(query[b,:], Wq[o,:]) + bq[o]   (fp32 exact)
// ---------------------------------------------------------------------------
__global__ void qproj_kernel(const float* __restrict__ query,
                             const float* __restrict__ Wq,
                             const float* __restrict__ bq) {
    __shared__ float q_s[H_DIM];
    const int b = blockIdx.x;
    const int tid = threadIdx.x;
    for (int i = tid; i < H_DIM; i += 256) q_s[i] = query[b * H_DIM + i];
    __syncthreads();
    const int warp = tid >> 5, lane = tid & 31;
    for (int o = warp; o < H_DIM; o += 8) {
        const float* wrow = Wq + (size_t)o * H_DIM;
        float s = 0.f;
        #pragma unroll 8
        for (int h = lane; h < H_DIM; h += 32) s += q_s[h] * wrow[h];
        #pragma unroll
        for (int m = 16; m > 0; m >>= 1) s += __shfl_xor_sync(0xffffffffu, s, m);
        if (lane == 0) g_qproj[b * H_DIM + o] = s + bq[o];
    }
}

// ---------------------------------------------------------------------------
// Kernel 2: fused score GEMM, tf32 mma.sync + ldmatrix.
//   score[r] = Vb + sum_o Vw[o]*tanh(qproj[b][o]+bv[o] + sum_k V[r][k]*Wv[o][k])
// Block tile 128(M) x 256(N), 4 N-passes, 512 threads = 16 warps (4m x 4n),
// warp tile 32x64 (proven R4 shape). BK=32, 2-stage cp.async pipeline.
// ---------------------------------------------------------------------------
#define BK       32
#define LDP      36                            // padded row stride (floats)
#define ST_A     (128 * LDP)                   // 4608 floats
#define ST_B     (256 * LDP)                   // 9216 floats
#define OFF_A    0
#define OFF_B    (2 * ST_A)
#define OFF_QB   (2 * ST_A + 2 * ST_B)
#define OFF_VW   (OFF_QB + 256)
#define OFF_SC   (OFF_VW + 256)
#define SMEM_FLT (OFF_SC + 128)
#define SMEM_BYTES (SMEM_FLT * 4)
#define NPASS    4
#define BN       256
#define NTHR     512

__device__ __forceinline__ void load_tile_a(float* dst, const float* __restrict__ src,
                                            int k0, int tid) {
    #pragma unroll
    for (int it = 0; it < 2; ++it) {           // 128 rows x 8 chunks = 1024
        int idx = it * NTHR + tid;
        int row = idx >> 3, ch = idx & 7;
        cp_async16(smem_u32(dst + row * LDP + ch * 4),
                   src + (size_t)row * H_DIM + k0 + ch * 4);
    }
}
__device__ __forceinline__ void load_tile_b(float* dst, const float* __restrict__ src,
                                            int k0, int tid) {
    #pragma unroll
    for (int it = 0; it < 4; ++it) {           // 256 rows x 8 chunks = 2048
        int idx = it * NTHR + tid;
        int row = idx >> 3, ch = idx & 7;
        cp_async16(smem_u32(dst + row * LDP + ch * 4),
                   src + (size_t)row * H_DIM + k0 + ch * 4);
    }
}

__global__ void __launch_bounds__(NTHR, 1) score_kernel(
    const float* __restrict__ values,
    const float* __restrict__ Wv,
    const float* __restrict__ bv,
    const float* __restrict__ Vw,
    const float* __restrict__ Vb) {

    extern __shared__ __align__(16) float smem[];
    float* As = smem + OFF_A;            // [2][128][36]
    float* Bs = smem + OFF_B;            // [2][256][36]
    float* qb_s = smem + OFF_QB;
    float* vw_s = smem + OFF_VW;
    float* score_s = smem + OFF_SC;

    const int tid = threadIdx.x;
    const int wid = tid >> 5, lane = tid & 31;
    const int warp_m = wid >> 2, warp_n = wid & 3;   // 4 x 4
    const int gid = lane >> 2, tig = lane & 3;
    const int l8 = lane & 7, sel = lane >> 3;

    const int r0 = blockIdx.x * 128;
    const int b  = r0 / T_DIM;
    const float* qp = g_qproj + b * H_DIM;
    const float* vrow0 = values + (size_t)r0 * H_DIM;

    if (tid < 128) score_s[tid] = 0.f;

    // ldmatrix lane addressing (fragment mapping validated in R4)
    const int a_row = warp_m * 32 + ((sel & 1) ? 8 : 0) + l8;
    const int a_kof = (sel & 2) ? 4 : 0;
    const int b_row = warp_n * 64 + ((sel & 2) ? 8 : 0) + l8;
    const int b_kof = (sel & 1) ? 4 : 0;

    float sacc[4] = {0.f, 0.f, 0.f, 0.f};

    for (int pass = 0; pass < NPASS; ++pass) {
        const int ob = pass * BN;
        __syncthreads();                 // prev pass fully done (incl. epilogue reads)
        if (tid < 256) {
            qb_s[tid] = qp[ob + tid] + bv[ob + tid];
            vw_s[tid] = Vw[ob + tid];
        }

        float c[2][8][4];
        #pragma unroll
        for (int mt = 0; mt < 2; ++mt)
            #pragma unroll
            for (int nt = 0; nt < 8; ++nt)
                #pragma unroll
                for (int i = 0; i < 4; ++i) c[mt][nt][i] = 0.f;

        load_tile_a(As, vrow0, 0, tid);
        load_tile_b(Bs, Wv + (size_t)ob * H_DIM, 0, tid);
        cp_commit();

        for (int kt = 0; kt < H_DIM / BK; ++kt) {
            const int cur = kt & 1;
            if (kt + 1 < H_DIM / BK) {
                const int nxt = cur ^ 1;
                load_tile_a(As + nxt * ST_A, vrow0, (kt + 1) * BK, tid);
                load_tile_b(Bs + nxt * ST_B, Wv + (size_t)ob * H_DIM, (kt + 1) * BK, tid);
                cp_commit();
                cp_wait<1>();
            } else {
                cp_wait<0>();
            }
            __syncthreads();

            const uint32_t a_base = smem_u32(As + cur * ST_A + a_row * LDP + a_kof);
            const uint32_t b_base = smem_u32(Bs + cur * ST_B + b_row * LDP + b_kof);

            #pragma unroll
            for (int ks = 0; ks < 4; ++ks) {
                const uint32_t koff = ks * 32;   // 8 floats
                uint32_t af[2][4], bf[8][2];
                #pragma unroll
                for (int mt = 0; mt < 2; ++mt)
                    ldsm_x4(af[mt], a_base + mt * (16 * LDP * 4) + koff);
                #pragma unroll
                for (int np = 0; np < 4; ++np) {
                    uint32_t r[4];
                    ldsm_x4(r, b_base + np * (16 * LDP * 4) + koff);
                    bf[np * 2 + 0][0] = r[0];
                    bf[np * 2 + 0][1] = r[1];
                    bf[np * 2 + 1][0] = r[2];
                    bf[np * 2 + 1][1] = r[3];
                }
                #pragma unroll
                for (int mt = 0; mt < 2; ++mt)
                    #pragma unroll
                    for (int nt = 0; nt < 8; ++nt)
                        mma_tf32(c[mt][nt], af[mt], bf[nt]);
            }
            __syncthreads();
        }

        // Epilogue: tanh + Vw contraction into per-lane row partials
        #pragma unroll
        for (int nt = 0; nt < 8; ++nt) {
            const int col0 = warp_n * 64 + nt * 8 + 2 * tig;
            const float vw0 = vw_s[col0],     qb0 = qb_s[col0];
            const float vw1 = vw_s[col0 + 1], qb1 = qb_s[col0 + 1];
            #pragma unroll
            for (int mt = 0; mt < 2; ++mt) {
                sacc[mt * 2 + 0] += vw0 * fast_tanh(c[mt][nt][0] + qb0)
                                  + vw1 * fast_tanh(c[mt][nt][1] + qb1);
                sacc[mt * 2 + 1] += vw0 * fast_tanh(c[mt][nt][2] + qb0)
                                  + vw1 * fast_tanh(c[mt][nt][3] + qb1);
            }
        }
    }

    // reduce over the 4 tig lanes, then combine the 4 n-warps via smem atomics
    #pragma unroll
    for (int i = 0; i < 4; ++i) {
        sacc[i] += __shfl_xor_sync(0xffffffffu, sacc[i], 1);
        sacc[i] += __shfl_xor_sync(0xffffffffu, sacc[i], 2);
    }
    if (tig == 0) {
        #pragma unroll
        for (int i = 0; i < 4; ++i) {
            const int row = warp_m * 32 + (i >> 1) * 16 + gid + (i & 1) * 8;
            atomicAdd(&score_s[row], sacc[i]);
        }
    }
    __syncthreads();
    if (tid < 128) g_score[r0 + tid] = score_s[tid] + Vb[0];
}

// ---------------------------------------------------------------------------
// Kernel 3: softmax over T per batch. Writes weights into d_out[B*H ..].
// ---------------------------------------------------------------------------
__global__ void softmax_kernel(float* __restrict__ d_out) {
    __shared__ float red[1024];
    const int b = blockIdx.x;
    const int tid = threadIdx.x;
    const float s0 = g_score[b * T_DIM + tid];
    const float s1 = g_score[b * T_DIM + 1024 + tid];
    red[tid] = fmaxf(s0, s1);
    __syncthreads();
    for (int s = 512; s > 0; s >>= 1) {
        if (tid < s) red[tid] = fmaxf(red[tid], red[tid + s]);
        __syncthreads();
    }
    const float mx = red[0];
    __syncthreads();
    const float e0 = expf(s0 - mx), e1 = expf(s1 - mx);
    red[tid] = e0 + e1;
    __syncthreads();
    for (int s = 512; s > 0; s >>= 1) {
        if (tid < s) red[tid] += red[tid + s];
        __syncthreads();
    }
    const float inv = 1.f / red[0];
    float* w = d_out + B_DIM * H_DIM + b * T_DIM;
    w[tid] = e0 * inv;
    w[tid + 1024] = e1 * inv;
}

// ---------------------------------------------------------------------------
// Kernel 4a: context partials over T chunks; 4b: deterministic reduce.
// ---------------------------------------------------------------------------
__global__ void __launch_bounds__(1024) ctx_partial_kernel(
    const float* __restrict__ values, const float* __restrict__ d_out_w) {
    __shared__ float w_s[256];
    const int ts = blockIdx.x, b = blockIdx.y;
    const int h = threadIdx.x;
    const float* w = d_out_w + b * T_DIM + ts * 256;
    if (h < 256) w_s[h] = w[h];
    __syncthreads();
    const float* vp = values + ((size_t)b * T_DIM + ts * 256) * H_DIM + h;
    float a0 = 0.f, a1 = 0.f, a2 = 0.f, a3 = 0.f;
    #pragma unroll 8
    for (int t = 0; t < 256; t += 4) {
        a0 += w_s[t + 0] * vp[(size_t)(t + 0) * H_DIM];
        a1 += w_s[t + 1] * vp[(size_t)(t + 1) * H_DIM];
        a2 += w_s[t + 2] * vp[(size_t)(t + 2) * H_DIM];
        a3 += w_s[t + 3] * vp[(size_t)(t + 3) * H_DIM];
    }
    g_ctx_part[(b * 8 + ts) * H_DIM + h] = (a0 + a1) + (a2 + a3);
}

__global__ void __launch_bounds__(1024) ctx_reduce_kernel(float* __restrict__ d_out) {
    const int b = blockIdx.x, h = threadIdx.x;
    float s = 0.f;
    #pragma unroll
    for (int ts = 0; ts < 8; ++ts) s += g_ctx_part[(b * 8 + ts) * H_DIM + h];
    d_out[b * H_DIM + h] = s;
}

// ---------------------------------------------------------------------------
extern "C" void kernel_launch(void* const* d_in, const int* in_sizes, int n_in,
                              void* d_out, int out_size) {
    const float* query  = (const float*)d_in[0];
    const float* values = (const float*)d_in[1];
    const float* Wq     = (const float*)d_in[2];
    const float* bq     = (const float*)d_in[3];
    const float* Wv     = (const float*)d_in[4];
    const float* bv     = (const float*)d_in[5];
    const float* Vw     = (const float*)d_in[6];
    const float* Vb     = (const float*)d_in[7];
    float* out = (float*)d_out;

    cudaFuncSetAttribute(score_kernel, cudaFuncAttributeMaxDynamicSharedMemorySize,
                         SMEM_BYTES);

    qproj_kernel<<<B_DIM, 256>>>(query, Wq, bq);
    score_kernel<<<(B_DIM * T_DIM) / 128, NTHR, SMEM_BYTES>>>(values, Wv, bv, Vw, Vb);
    softmax_kernel<<<B_DIM, 1024>>>(out);
    ctx_partial_kernel<<<dim3(8, B_DIM), 1024>>>(values, out + B_DIM * H_DIM);
    ctx_reduce_kernel<<<B_DIM, 1024>>>(out);
}

// round 7
// speedup vs baseline: 1.3720x; 1.3091x over previous
#include <cuda_runtime.h>
#include <cuda_fp16.h>
#include <math.h>
#include <stdint.h>

#define B_DIM 32
#define T_DIM 2048
#define H_DIM 1024

// ---------------------------------------------------------------------------
// Scratch (allocation-free rule: __device__ globals)
// ---------------------------------------------------------------------------
__device__ float  g_qproj[B_DIM * H_DIM];
__device__ float  g_score[B_DIM * T_DIM];
__device__ float  g_ctx_part[B_DIM * 8 * H_DIM];
__device__ __half g_vals_h[(size_t)B_DIM * T_DIM * H_DIM];   // 128 MB
__device__ __half g_wv_h[H_DIM * H_DIM];

// ---------------------------------------------------------------------------
// PTX helpers (sm_80-compatible; tcgen05 is NOT available at compute_103)
// ---------------------------------------------------------------------------
__device__ __forceinline__ uint32_t smem_u32(const void* p) {
    uint32_t a;
    asm("{ .reg .u64 t; cvta.to.shared.u64 t, %1; cvt.u32.u64 %0, t; }" : "=r"(a) : "l"(p));
    return a;
}
__device__ __forceinline__ void cp_async16(uint32_t dst, const void* src) {
    asm volatile("cp.async.cg.shared.global [%0], [%1], 16;" :: "r"(dst), "l"(src));
}
__device__ __forceinline__ void cp_commit() {
    asm volatile("cp.async.commit_group;" ::: "memory");
}
template <int N>
__device__ __forceinline__ void cp_wait() {
    asm volatile("cp.async.wait_group %0;" :: "n"(N) : "memory");
}
__device__ __forceinline__ void ldsm_x4(uint32_t r[4], uint32_t addr) {
    asm volatile("ldmatrix.sync.aligned.m8n8.x4.shared.b16 {%0,%1,%2,%3}, [%4];"
                 : "=r"(r[0]), "=r"(r[1]), "=r"(r[2]), "=r"(r[3]) : "r"(addr));
}
__device__ __forceinline__ void mma_f16(float c[4], const uint32_t a[4], const uint32_t b[2]) {
    asm volatile(
        "mma.sync.aligned.m16n8k16.row.col.f32.f16.f16.f32 "
        "{%0,%1,%2,%3}, {%4,%5,%6,%7}, {%8,%9}, {%0,%1,%2,%3};"
        : "+f"(c[0]), "+f"(c[1]), "+f"(c[2]), "+f"(c[3])
        : "r"(a[0]), "r"(a[1]), "r"(a[2]), "r"(a[3]), "r"(b[0]), "r"(b[1]));
}
__device__ __forceinline__ float fast_tanh(float x) {
    float e = __expf(2.0f * x);
    return 1.0f - 2.0f / (e + 1.0f);
}

// ---------------------------------------------------------------------------
// Kernel 0: fp32 -> fp16 conversion (grid-stride over float4)
// ---------------------------------------------------------------------------
__global__ void convert_kernel(const float* __restrict__ src, __half* __restrict__ dst,
                               int n4) {
    int i = blockIdx.x * blockDim.x + threadIdx.x;
    const int stride = gridDim.x * blockDim.x;
    for (; i < n4; i += stride) {
        float4 v = ((const float4*)src)[i];
        __half2 h0 = __floats2half2_rn(v.x, v.y);
        __half2 h1 = __floats2half2_rn(v.z, v.w);
        ((__half2*)dst)[2 * i + 0] = h0;
        ((__half2*)dst)[2 * i + 1] = h1;
    }
}

// ---------------------------------------------------------------------------
// Kernel 1: q_proj[b][o] = dot(query[b,:], Wq[o,:]) + bq[o]   (fp32 exact)
// ---------------------------------------------------------------------------
__global__ void qproj_kernel(const float* __restrict__ query,
                             const float* __restrict__ Wq,
                             const float* __restrict__ bq) {
    __shared__ float q_s[H_DIM];
    const int b = blockIdx.x;
    const int tid = threadIdx.x;
    for (int i = tid; i < H_DIM; i += 256) q_s[i] = query[b * H_DIM + i];
    __syncthreads();
    const int warp = tid >> 5, lane = tid & 31;
    for (int o = warp; o < H_DIM; o += 8) {
        const float* wrow = Wq + (size_t)o * H_DIM;
        float s = 0.f;
        #pragma unroll 8
        for (int h = lane; h < H_DIM; h += 32) s += q_s[h] * wrow[h];
        #pragma unroll
        for (int m = 16; m > 0; m >>= 1) s += __shfl_xor_sync(0xffffffffu, s, m);
        if (lane == 0) g_qproj[b * H_DIM + o] = s + bq[o];
    }
}

// ---------------------------------------------------------------------------
// Kernel 2: fused score GEMM, fp16 m16n8k16 mma.sync + ldmatrix.
//   score[r] = Vb + sum_o Vw[o]*tanh(qproj[b][o]+bv[o] + sum_k V[r][k]*Wv[o][k])
// Block 128x128 per pass, 8 passes. 256 threads = 8 warps (4m x 2n),
// warp tile 32x64. BK=32 halves, 2-stage cp.async pipeline. fp32 accum.
// ---------------------------------------------------------------------------
#define BK       32
#define LDPH     40                            // padded row stride (halves), 80B
#define ST_AH    (128 * LDPH)                  // halves per A stage
#define ST_BH    (128 * LDPH)
#define OFF_AH   0
#define OFF_BH   (2 * ST_AH)
#define HALVES   (2 * ST_AH + 2 * ST_BH)       // 20480 halves = 40960 B
#define OFF_QB   (HALVES / 2)                  // float index
#define OFF_VW   (OFF_QB + 128)
#define OFF_SC   (OFF_VW + 128)
#define SMEM_FLT (OFF_SC + 128)
#define SMEM_BYTES (SMEM_FLT * 4)

__device__ __forceinline__ void load_tile_h(__half* dst, const __half* __restrict__ src,
                                            int k0, int tid) {
    // 128 rows x 32 halves (4 x 16B chunks per row); 256 threads, 2 iters
    #pragma unroll
    for (int it = 0; it < 2; ++it) {
        int idx = it * 256 + tid;
        int row = idx >> 2, ch = idx & 3;
        cp_async16(smem_u32(dst + row * LDPH + ch * 8),
                   src + (size_t)row * H_DIM + k0 + ch * 8);
    }
}

__global__ void __launch_bounds__(256, 2) score_kernel(
    const float* __restrict__ bv,
    const float* __restrict__ Vw,
    const float* __restrict__ Vb) {

    extern __shared__ __align__(16) float smem[];
    __half* As = (__half*)smem + OFF_AH;      // [2][128][40]
    __half* Bs = (__half*)smem + OFF_BH;
    float* qb_s = smem + OFF_QB;
    float* vw_s = smem + OFF_VW;
    float* score_s = smem + OFF_SC;

    const int tid = threadIdx.x;
    const int wid = tid >> 5, lane = tid & 31;
    const int warp_m = wid >> 1, warp_n = wid & 1;   // 4 x 2
    const int gid = lane >> 2, tig = lane & 3;
    const int l8 = lane & 7, sel = lane >> 3;

    const int r0 = blockIdx.x * 128;
    const int b  = r0 / T_DIM;
    const float* qp = g_qproj + b * H_DIM;
    const __half* vrow0 = g_vals_h + (size_t)r0 * H_DIM;

    if (tid < 128) score_s[tid] = 0.f;

    // ldmatrix lane addressing (halves):
    //  A x4: m0=(r,k0-7) m1=(r+8,k0-7) m2=(r,k8-15) m3=(r+8,k8-15)
    const int a_row = warp_m * 32 + ((sel & 1) ? 8 : 0) + l8;
    const int a_kof = (sel & 2) ? 8 : 0;
    //  B x4: m0=(n,k0-7) m1=(n,k8-15) m2=(n+8,k0-7) m3=(n+8,k8-15)
    const int b_row = warp_n * 64 + ((sel & 2) ? 8 : 0) + l8;
    const int b_kof = (sel & 1) ? 8 : 0;

    float sacc[4] = {0.f, 0.f, 0.f, 0.f};

    for (int oc = 0; oc < 8; ++oc) {
        const int ob = oc * 128;
        __syncthreads();
        if (tid < 128) {
            qb_s[tid] = qp[ob + tid] + bv[ob + tid];
            vw_s[tid] = Vw[ob + tid];
        }

        float c[2][8][4];
        #pragma unroll
        for (int mt = 0; mt < 2; ++mt)
            #pragma unroll
            for (int nt = 0; nt < 8; ++nt)
                #pragma unroll
                for (int i = 0; i < 4; ++i) c[mt][nt][i] = 0.f;

        load_tile_h(As, vrow0, 0, tid);
        load_tile_h(Bs, g_wv_h + (size_t)ob * H_DIM, 0, tid);
        cp_commit();

        for (int kt = 0; kt < H_DIM / BK; ++kt) {
            const int cur = kt & 1;
            if (kt + 1 < H_DIM / BK) {
                const int nxt = cur ^ 1;
                load_tile_h(As + nxt * ST_AH, vrow0, (kt + 1) * BK, tid);
                load_tile_h(Bs + nxt * ST_BH, g_wv_h + (size_t)ob * H_DIM,
                            (kt + 1) * BK, tid);
                cp_commit();
                cp_wait<1>();
            } else {
                cp_wait<0>();
            }
            __syncthreads();

            const uint32_t a_base = smem_u32(As + cur * ST_AH + a_row * LDPH + a_kof);
            const uint32_t b_base = smem_u32(Bs + cur * ST_BH + b_row * LDPH + b_kof);

            #pragma unroll
            for (int ks = 0; ks < 2; ++ks) {                 // two k16 steps
                const uint32_t koff = ks * 32;               // 16 halves = 32B
                uint32_t af[2][4], bf[8][2];
                #pragma unroll
                for (int mt = 0; mt < 2; ++mt)
                    ldsm_x4(af[mt], a_base + mt * (16 * LDPH * 2) + koff);
                #pragma unroll
                for (int np = 0; np < 4; ++np) {
                    uint32_t r[4];
                    ldsm_x4(r, b_base + np * (16 * LDPH * 2) + koff);
                    bf[np * 2 + 0][0] = r[0];   // (n0-7, k0-7)
                    bf[np * 2 + 0][1] = r[1];   // (n0-7, k8-15)
                    bf[np * 2 + 1][0] = r[2];   // (n+8, k0-7)
                    bf[np * 2 + 1][1] = r[3];   // (n+8, k8-15)
                }
                #pragma unroll
                for (int mt = 0; mt < 2; ++mt)
                    #pragma unroll
                    for (int nt = 0; nt < 8; ++nt)
                        mma_f16(c[mt][nt], af[mt], bf[nt]);
            }
            __syncthreads();
        }

        // Epilogue: tanh + Vw contraction into per-lane row partials
        #pragma unroll
        for (int nt = 0; nt < 8; ++nt) {
            const int col0 = warp_n * 64 + nt * 8 + 2 * tig;
            const float vw0 = vw_s[col0],     qb0 = qb_s[col0];
            const float vw1 = vw_s[col0 + 1], qb1 = qb_s[col0 + 1];
            #pragma unroll
            for (int mt = 0; mt < 2; ++mt) {
                sacc[mt * 2 + 0] += vw0 * fast_tanh(c[mt][nt][0] + qb0)
                                  + vw1 * fast_tanh(c[mt][nt][1] + qb1);
                sacc[mt * 2 + 1] += vw0 * fast_tanh(c[mt][nt][2] + qb0)
                                  + vw1 * fast_tanh(c[mt][nt][3] + qb1);
            }
        }
    }

    #pragma unroll
    for (int i = 0; i < 4; ++i) {
        sacc[i] += __shfl_xor_sync(0xffffffffu, sacc[i], 1);
        sacc[i] += __shfl_xor_sync(0xffffffffu, sacc[i], 2);
    }
    if (tig == 0) {
        #pragma unroll
        for (int i = 0; i < 4; ++i) {
            const int row = warp_m * 32 + (i >> 1) * 16 + gid + (i & 1) * 8;
            atomicAdd(&score_s[row], sacc[i]);
        }
    }
    __syncthreads();
    if (tid < 128) g_score[r0 + tid] = score_s[tid] + Vb[0];
}

// ---------------------------------------------------------------------------
// Kernel 3: softmax over T per batch. Writes weights into d_out[B*H ..].
// ---------------------------------------------------------------------------
__global__ void softmax_kernel(float* __restrict__ d_out) {
    __shared__ float red[1024];
    const int b = blockIdx.x;
    const int tid = threadIdx.x;
    const float s0 = g_score[b * T_DIM + tid];
    const float s1 = g_score[b * T_DIM + 1024 + tid];
    red[tid] = fmaxf(s0, s1);
    __syncthreads();
    for (int s = 512; s > 0; s >>= 1) {
        if (tid < s) red[tid] = fmaxf(red[tid], red[tid + s]);
        __syncthreads();
    }
    const float mx = red[0];
    __syncthreads();
    const float e0 = expf(s0 - mx), e1 = expf(s1 - mx);
    red[tid] = e0 + e1;
    __syncthreads();
    for (int s = 512; s > 0; s >>= 1) {
        if (tid < s) red[tid] += red[tid + s];
        __syncthreads();
    }
    const float inv = 1.f / red[0];
    float* w = d_out + B_DIM * H_DIM + b * T_DIM;
    w[tid] = e0 * inv;
    w[tid + 1024] = e1 * inv;
}

// ---------------------------------------------------------------------------
// Kernel 4a: context partials over T chunks; 4b: deterministic reduce.
// (fp32 exact, reads original values)
// ---------------------------------------------------------------------------
__global__ void __launch_bounds__(1024) ctx_partial_kernel(
    const float* __restrict__ values, const float* __restrict__ d_out_w) {
    __shared__ float w_s[256];
    const int ts = blockIdx.x, b = blockIdx.y;
    const int h = threadIdx.x;
    const float* w = d_out_w + b * T_DIM + ts * 256;
    if (h < 256) w_s[h] = w[h];
    __syncthreads();
    const float* vp = values + ((size_t)b * T_DIM + ts * 256) * H_DIM + h;
    float a0 = 0.f, a1 = 0.f, a2 = 0.f, a3 = 0.f;
    #pragma unroll 8
    for (int t = 0; t < 256; t += 4) {
        a0 += w_s[t + 0] * vp[(size_t)(t + 0) * H_DIM];
        a1 += w_s[t + 1] * vp[(size_t)(t + 1) * H_DIM];
        a2 += w_s[t + 2] * vp[(size_t)(t + 2) * H_DIM];
        a3 += w_s[t + 3] * vp[(size_t)(t + 3) * H_DIM];
    }
    g_ctx_part[(b * 8 + ts) * H_DIM + h] = (a0 + a1) + (a2 + a3);
}

__global__ void __launch_bounds__(1024) ctx_reduce_kernel(float* __restrict__ d_out) {
    const int b = blockIdx.x, h = threadIdx.x;
    float s = 0.f;
    #pragma unroll
    for (int ts = 0; ts < 8; ++ts) s += g_ctx_part[(b * 8 + ts) * H_DIM + h];
    d_out[b * H_DIM + h] = s;
}

// ---------------------------------------------------------------------------
extern "C" void kernel_launch(void* const* d_in, const int* in_sizes, int n_in,
                              void* d_out, int out_size) {
    const float* query  = (const float*)d_in[0];
    const float* values = (const float*)d_in[1];
    const float* Wq     = (const float*)d_in[2];
    const float* bq     = (const float*)d_in[3];
    const float* Wv     = (const float*)d_in[4];
    const float* bv     = (const float*)d_in[5];
    const float* Vw     = (const float*)d_in[6];
    const float* Vb     = (const float*)d_in[7];
    float* out = (float*)d_out;

    cudaFuncSetAttribute(score_kernel, cudaFuncAttributeMaxDynamicSharedMemorySize,
                         SMEM_BYTES);

    __half* vals_h;
    cudaGetSymbolAddress((void**)&vals_h, g_vals_h);
    __half* wv_h;
    cudaGetSymbolAddress((void**)&wv_h, g_wv_h);

    convert_kernel<<<8192, 256>>>(values, vals_h, (B_DIM * T_DIM * (H_DIM / 4)));
    convert_kernel<<<2048, 256>>>(Wv, wv_h, (H_DIM * H_DIM) / 4);
    qproj_kernel<<<B_DIM, 256>>>(query, Wq, bq);
    score_kernel<<<(B_DIM * T_DIM) / 128, 256, SMEM_BYTES>>>(bv, Vw, Vb);
    softmax_kernel<<<B_DIM, 1024>>>(out);
    ctx_partial_kernel<<<dim3(8, B_DIM), 1024>>>(values, out + B_DIM * H_DIM);
    ctx_reduce_kernel<<<B_DIM, 1024>>>(out);
}

// round 8
// speedup vs baseline: 1.5434x; 1.1250x over previous
#include <cuda_runtime.h>
#include <cuda_fp16.h>
#include <math.h>
#include <stdint.h>

#define B_DIM 32
#define T_DIM 2048
#define H_DIM 1024

// ---------------------------------------------------------------------------
// Scratch (allocation-free rule: __device__ globals)
// ---------------------------------------------------------------------------
__device__ float  g_qproj[B_DIM * H_DIM];
__device__ float  g_score[B_DIM * T_DIM];
__device__ float  g_ctx_part[B_DIM * 8 * H_DIM];
__device__ __half g_vals_h[(size_t)B_DIM * T_DIM * H_DIM];   // 128 MB
__device__ __half g_wv_h[H_DIM * H_DIM];

// ---------------------------------------------------------------------------
// PTX helpers (sm_80-compatible; tcgen05 is NOT available at compute_103)
// ---------------------------------------------------------------------------
__device__ __forceinline__ uint32_t smem_u32(const void* p) {
    uint32_t a;
    asm("{ .reg .u64 t; cvta.to.shared.u64 t, %1; cvt.u32.u64 %0, t; }" : "=r"(a) : "l"(p));
    return a;
}
__device__ __forceinline__ void cp_async16(uint32_t dst, const void* src) {
    asm volatile("cp.async.cg.shared.global [%0], [%1], 16;" :: "r"(dst), "l"(src));
}
__device__ __forceinline__ void cp_commit() {
    asm volatile("cp.async.commit_group;" ::: "memory");
}
template <int N>
__device__ __forceinline__ void cp_wait() {
    asm volatile("cp.async.wait_group %0;" :: "n"(N) : "memory");
}
__device__ __forceinline__ void ldsm_x4(uint32_t r[4], uint32_t addr) {
    asm volatile("ldmatrix.sync.aligned.m8n8.x4.shared.b16 {%0,%1,%2,%3}, [%4];"
                 : "=r"(r[0]), "=r"(r[1]), "=r"(r[2]), "=r"(r[3]) : "r"(addr));
}
__device__ __forceinline__ void mma_f16(float c[4], const uint32_t a[4], const uint32_t b[2]) {
    asm volatile(
        "mma.sync.aligned.m16n8k16.row.col.f32.f16.f16.f32 "
        "{%0,%1,%2,%3}, {%4,%5,%6,%7}, {%8,%9}, {%0,%1,%2,%3};"
        : "+f"(c[0]), "+f"(c[1]), "+f"(c[2]), "+f"(c[3])
        : "r"(a[0]), "r"(a[1]), "r"(a[2]), "r"(a[3]), "r"(b[0]), "r"(b[1]));
}
__device__ __forceinline__ float fast_tanh(float x) {
    float e = __expf(2.0f * x);
    return 1.0f - 2.0f / (e + 1.0f);
}

// ---------------------------------------------------------------------------
// Kernel 0: fp32 -> fp16 conversion (grid-stride over float4)
// ---------------------------------------------------------------------------
__global__ void convert_kernel(const float* __restrict__ src, __half* __restrict__ dst,
                               int n4) {
    int i = blockIdx.x * blockDim.x + threadIdx.x;
    const int stride = gridDim.x * blockDim.x;
    for (; i < n4; i += stride) {
        float4 v = ((const float4*)src)[i];
        __half2 h0 = __floats2half2_rn(v.x, v.y);
        __half2 h1 = __floats2half2_rn(v.z, v.w);
        ((__half2*)dst)[2 * i + 0] = h0;
        ((__half2*)dst)[2 * i + 1] = h1;
    }
}

// ---------------------------------------------------------------------------
// Kernel 1: q_proj[b][o] = dot(query[b,:], Wq[o,:]) + bq[o]   (fp32 exact)
// ---------------------------------------------------------------------------
__global__ void qproj_kernel(const float* __restrict__ query,
                             const float* __restrict__ Wq,
                             const float* __restrict__ bq) {
    __shared__ float q_s[H_DIM];
    const int b = blockIdx.x;
    const int tid = threadIdx.x;
    for (int i = tid; i < H_DIM; i += 256) q_s[i] = query[b * H_DIM + i];
    __syncthreads();
    const int warp = tid >> 5, lane = tid & 31;
    for (int o = warp; o < H_DIM; o += 8) {
        const float* wrow = Wq + (size_t)o * H_DIM;
        float s = 0.f;
        #pragma unroll 8
        for (int h = lane; h < H_DIM; h += 32) s += q_s[h] * wrow[h];
        #pragma unroll
        for (int m = 16; m > 0; m >>= 1) s += __shfl_xor_sync(0xffffffffu, s, m);
        if (lane == 0) g_qproj[b * H_DIM + o] = s + bq[o];
    }
}

// ---------------------------------------------------------------------------
// Kernel 2: fused score GEMM, fp16 m16n8k16 mma.sync + ldmatrix.
// 4-stage cp.async pipeline, ONE __syncthreads per K-iteration.
// Block 128x128 per pass, 8 passes. 256 threads = 8 warps (4m x 2n),
// warp tile 32x64. BK=32 halves. fp32 accum.
// ---------------------------------------------------------------------------
#define BK       32
#define STAGES   4
#define NKT      (H_DIM / BK)                  // 32
#define LDPH     40                            // padded row stride (halves), 80B
#define ST_AH    (128 * LDPH)                  // halves per stage
#define ST_BH    (128 * LDPH)
#define OFF_AH   0
#define OFF_BH   (STAGES * ST_AH)
#define HALVES   (2 * STAGES * ST_AH)
#define OFF_QB   (HALVES / 2)                  // float index
#define OFF_VW   (OFF_QB + 128)
#define OFF_SC   (OFF_VW + 128)
#define SMEM_FLT (OFF_SC + 128)
#define SMEM_BYTES (SMEM_FLT * 4)

__device__ __forceinline__ void load_tile_h(__half* dst, const __half* __restrict__ src,
                                            int k0, int tid) {
    // 128 rows x 32 halves (4 x 16B chunks per row); 256 threads, 2 iters
    #pragma unroll
    for (int it = 0; it < 2; ++it) {
        int idx = it * 256 + tid;
        int row = idx >> 2, ch = idx & 3;
        cp_async16(smem_u32(dst + row * LDPH + ch * 8),
                   src + (size_t)row * H_DIM + k0 + ch * 8);
    }
}

__global__ void __launch_bounds__(256, 2) score_kernel(
    const float* __restrict__ bv,
    const float* __restrict__ Vw,
    const float* __restrict__ Vb) {

    extern __shared__ __align__(16) float smem[];
    __half* As = (__half*)smem + OFF_AH;      // [STAGES][128][40]
    __half* Bs = (__half*)smem + OFF_BH;
    float* qb_s = smem + OFF_QB;
    float* vw_s = smem + OFF_VW;
    float* score_s = smem + OFF_SC;

    const int tid = threadIdx.x;
    const int wid = tid >> 5, lane = tid & 31;
    const int warp_m = wid >> 1, warp_n = wid & 1;   // 4 x 2
    const int gid = lane >> 2, tig = lane & 3;
    const int l8 = lane & 7, sel = lane >> 3;

    const int r0 = blockIdx.x * 128;
    const int b  = r0 / T_DIM;
    const float* qp = g_qproj + b * H_DIM;
    const __half* vrow0 = g_vals_h + (size_t)r0 * H_DIM;

    if (tid < 128) score_s[tid] = 0.f;

    // ldmatrix lane addressing (halves):
    const int a_row = warp_m * 32 + ((sel & 1) ? 8 : 0) + l8;
    const int a_kof = (sel & 2) ? 8 : 0;
    const int b_row = warp_n * 64 + ((sel & 2) ? 8 : 0) + l8;
    const int b_kof = (sel & 1) ? 8 : 0;

    float sacc[4] = {0.f, 0.f, 0.f, 0.f};

    for (int oc = 0; oc < 8; ++oc) {
        const int ob = oc * 128;
        const __half* wvp = g_wv_h + (size_t)ob * H_DIM;
        __syncthreads();                 // prev pass fully done (epilogue + stage reuse)
        if (tid < 128) {
            qb_s[tid] = qp[ob + tid] + bv[ob + tid];
            vw_s[tid] = Vw[ob + tid];
        }

        float c[2][8][4];
        #pragma unroll
        for (int mt = 0; mt < 2; ++mt)
            #pragma unroll
            for (int nt = 0; nt < 8; ++nt)
                #pragma unroll
                for (int i = 0; i < 4; ++i) c[mt][nt][i] = 0.f;

        // prologue: fill stages 0..STAGES-2
        #pragma unroll
        for (int s = 0; s < STAGES - 1; ++s) {
            load_tile_h(As + s * ST_AH, vrow0, s * BK, tid);
            load_tile_h(Bs + s * ST_BH, wvp, s * BK, tid);
            cp_commit();
        }

        for (int kt = 0; kt < NKT; ++kt) {
            const int cur = kt & (STAGES - 1);
            cp_wait<STAGES - 2>();       // stage `cur` complete
            __syncthreads();             // all warps done with slot being refilled below

            const uint32_t a_base = smem_u32(As + cur * ST_AH + a_row * LDPH + a_kof);
            const uint32_t b_base = smem_u32(Bs + cur * ST_BH + b_row * LDPH + b_kof);

            #pragma unroll
            for (int ks = 0; ks < 2; ++ks) {                 // two k16 steps
                const uint32_t koff = ks * 32;               // 16 halves = 32B
                uint32_t af[2][4], bf[8][2];
                #pragma unroll
                for (int mt = 0; mt < 2; ++mt)
                    ldsm_x4(af[mt], a_base + mt * (16 * LDPH * 2) + koff);
                #pragma unroll
                for (int np = 0; np < 4; ++np) {
                    uint32_t r[4];
                    ldsm_x4(r, b_base + np * (16 * LDPH * 2) + koff);
                    bf[np * 2 + 0][0] = r[0];
                    bf[np * 2 + 0][1] = r[1];
                    bf[np * 2 + 1][0] = r[2];
                    bf[np * 2 + 1][1] = r[3];
                }
                #pragma unroll
                for (int mt = 0; mt < 2; ++mt)
                    #pragma unroll
                    for (int nt = 0; nt < 8; ++nt)
                        mma_f16(c[mt][nt], af[mt], bf[nt]);
            }

            // refill the slot consumed at iteration kt-1 (ordered by the
            // barrier above); always commit to keep group arithmetic uniform
            const int nk = kt + STAGES - 1;
            if (nk < NKT) {
                const int ns = nk & (STAGES - 1);
                load_tile_h(As + ns * ST_AH, vrow0, nk * BK, tid);
                load_tile_h(Bs + ns * ST_BH, wvp, nk * BK, tid);
            }
            cp_commit();
        }

        // Epilogue: tanh + Vw contraction into per-lane row partials
        #pragma unroll
        for (int nt = 0; nt < 8; ++nt) {
            const int col0 = warp_n * 64 + nt * 8 + 2 * tig;
            const float vw0 = vw_s[col0],     qb0 = qb_s[col0];
            const float vw1 = vw_s[col0 + 1], qb1 = qb_s[col0 + 1];
            #pragma unroll
            for (int mt = 0; mt < 2; ++mt) {
                sacc[mt * 2 + 0] += vw0 * fast_tanh(c[mt][nt][0] + qb0)
                                  + vw1 * fast_tanh(c[mt][nt][1] + qb1);
                sacc[mt * 2 + 1] += vw0 * fast_tanh(c[mt][nt][2] + qb0)
                                  + vw1 * fast_tanh(c[mt][nt][3] + qb1);
            }
        }
    }

    #pragma unroll
    for (int i = 0; i < 4; ++i) {
        sacc[i] += __shfl_xor_sync(0xffffffffu, sacc[i], 1);
        sacc[i] += __shfl_xor_sync(0xffffffffu, sacc[i], 2);
    }
    if (tig == 0) {
        #pragma unroll
        for (int i = 0; i < 4; ++i) {
            const int row = warp_m * 32 + (i >> 1) * 16 + gid + (i & 1) * 8;
            atomicAdd(&score_s[row], sacc[i]);
        }
    }
    __syncthreads();
    if (tid < 128) g_score[r0 + tid] = score_s[tid] + Vb[0];
}

// ---------------------------------------------------------------------------
// Kernel 3: softmax over T per batch. Writes weights into d_out[B*H ..].
// ---------------------------------------------------------------------------
__global__ void softmax_kernel(float* __restrict__ d_out) {
    __shared__ float red[1024];
    const int b = blockIdx.x;
    const int tid = threadIdx.x;
    const float s0 = g_score[b * T_DIM + tid];
    const float s1 = g_score[b * T_DIM + 1024 + tid];
    red[tid] = fmaxf(s0, s1);
    __syncthreads();
    for (int s = 512; s > 0; s >>= 1) {
        if (tid < s) red[tid] = fmaxf(red[tid], red[tid + s]);
        __syncthreads();
    }
    const float mx = red[0];
    __syncthreads();
    const float e0 = expf(s0 - mx), e1 = expf(s1 - mx);
    red[tid] = e0 + e1;
    __syncthreads();
    for (int s = 512; s > 0; s >>= 1) {
        if (tid < s) red[tid] += red[tid + s];
        __syncthreads();
    }
    const float inv = 1.f / red[0];
    float* w = d_out + B_DIM * H_DIM + b * T_DIM;
    w[tid] = e0 * inv;
    w[tid + 1024] = e1 * inv;
}

// ---------------------------------------------------------------------------
// Kernel 4a: context partials over T chunks; 4b: deterministic reduce.
// ---------------------------------------------------------------------------
__global__ void __launch_bounds__(1024) ctx_partial_kernel(
    const float* __restrict__ values, const float* __restrict__ d_out_w) {
    __shared__ float w_s[256];
    const int ts = blockIdx.x, b = blockIdx.y;
    const int h = threadIdx.x;
    const float* w = d_out_w + b * T_DIM + ts * 256;
    if (h < 256) w_s[h] = w[h];
    __syncthreads();
    const float* vp = values + ((size_t)b * T_DIM + ts * 256) * H_DIM + h;
    float a0 = 0.f, a1 = 0.f, a2 = 0.f, a3 = 0.f;
    #pragma unroll 8
    for (int t = 0; t < 256; t += 4) {
        a0 += w_s[t + 0] * vp[(size_t)(t + 0) * H_DIM];
        a1 += w_s[t + 1] * vp[(size_t)(t + 1) * H_DIM];
        a2 += w_s[t + 2] * vp[(size_t)(t + 2) * H_DIM];
        a3 += w_s[t + 3] * vp[(size_t)(t + 3) * H_DIM];
    }
    g_ctx_part[(b * 8 + ts) * H_DIM + h] = (a0 + a1) + (a2 + a3);
}

__global__ void __launch_bounds__(1024) ctx_reduce_kernel(float* __restrict__ d_out) {
    const int b = blockIdx.x, h = threadIdx.x;
    float s = 0.f;
    #pragma unroll
    for (int ts = 0; ts < 8; ++ts) s += g_ctx_part[(b * 8 + ts) * H_DIM + h];
    d_out[b * H_DIM + h] = s;
}

// ---------------------------------------------------------------------------
extern "C" void kernel_launch(void* const* d_in, const int* in_sizes, int n_in,
                              void* d_out, int out_size) {
    const float* query  = (const float*)d_in[0];
    const float* values = (const float*)d_in[1];
    const float* Wq     = (const float*)d_in[2];
    const float* bq     = (const float*)d_in[3];
    const float* Wv     = (const float*)d_in[4];
    const float* bv     = (const float*)d_in[5];
    const float* Vw     = (const float*)d_in[6];
    const float* Vb     = (const float*)d_in[7];
    float* out = (float*)d_out;

    cudaFuncSetAttribute(score_kernel, cudaFuncAttributeMaxDynamicSharedMemorySize,
                         SMEM_BYTES);

    __half* vals_h;
    cudaGetSymbolAddress((void**)&vals_h, g_vals_h);
    __half* wv_h;
    cudaGetSymbolAddress((void**)&wv_h, g_wv_h);

    convert_kernel<<<8192, 256>>>(values, vals_h, (B_DIM * T_DIM * (H_DIM / 4)));
    convert_kernel<<<2048, 256>>>(Wv, wv_h, (H_DIM * H_DIM) / 4);
    qproj_kernel<<<B_DIM, 256>>>(query, Wq, bq);
    score_kernel<<<(B_DIM * T_DIM) / 128, 256, SMEM_BYTES>>>(bv, Vw, Vb);
    softmax_kernel<<<B_DIM, 1024>>>(out);
    ctx_partial_kernel<<<dim3(8, B_DIM), 1024>>>(values, out + B_DIM * H_DIM);
    ctx_reduce_kernel<<<B_DIM, 1024>>>(out);
}

// round 9
// speedup vs baseline: 2.0829x; 1.3495x over previous
#include <cuda_runtime.h>
#include <cuda_fp16.h>
#include <math.h>
#include <stdint.h>

#define B_DIM 32
#define T_DIM 2048
#define H_DIM 1024

// ---------------------------------------------------------------------------
// Scratch (allocation-free rule: __device__ globals)
// ---------------------------------------------------------------------------
__device__ float  g_qproj[B_DIM * H_DIM];
__device__ float  g_score[B_DIM * T_DIM];
__device__ float  g_ctx_part[B_DIM * 8 * H_DIM];
__device__ __half g_vals_h[(size_t)B_DIM * T_DIM * H_DIM];   // 128 MB
__device__ __half g_wv_h[H_DIM * H_DIM];

// ---------------------------------------------------------------------------
// PTX helpers (sm_80-compatible; tcgen05 is NOT available at compute_103)
// ---------------------------------------------------------------------------
__device__ __forceinline__ uint32_t smem_u32(const void* p) {
    uint32_t a;
    asm("{ .reg .u64 t; cvta.to.shared.u64 t, %1; cvt.u32.u64 %0, t; }" : "=r"(a) : "l"(p));
    return a;
}
__device__ __forceinline__ void cp_async16(uint32_t dst, const void* src) {
    asm volatile("cp.async.cg.shared.global [%0], [%1], 16;" :: "r"(dst), "l"(src));
}
__device__ __forceinline__ void cp_commit() {
    asm volatile("cp.async.commit_group;" ::: "memory");
}
template <int N>
__device__ __forceinline__ void cp_wait() {
    asm volatile("cp.async.wait_group %0;" :: "n"(N) : "memory");
}
__device__ __forceinline__ void ldsm_x4(uint32_t r[4], uint32_t addr) {
    asm volatile("ldmatrix.sync.aligned.m8n8.x4.shared.b16 {%0,%1,%2,%3}, [%4];"
                 : "=r"(r[0]), "=r"(r[1]), "=r"(r[2]), "=r"(r[3]) : "r"(addr));
}
__device__ __forceinline__ void mma_f16(float c[4], const uint32_t a[4], const uint32_t b[2]) {
    asm volatile(
        "mma.sync.aligned.m16n8k16.row.col.f32.f16.f16.f32 "
        "{%0,%1,%2,%3}, {%4,%5,%6,%7}, {%8,%9}, {%0,%1,%2,%3};"
        : "+f"(c[0]), "+f"(c[1]), "+f"(c[2]), "+f"(c[3])
        : "r"(a[0]), "r"(a[1]), "r"(a[2]), "r"(a[3]), "r"(b[0]), "r"(b[1]));
}
__device__ __forceinline__ float fast_tanh(float x) {
    float e = __expf(2.0f * x);
    return 1.0f - 2.0f / (e + 1.0f);
}

// ---------------------------------------------------------------------------
// Kernel 0: fp32 -> fp16 conversion (grid-stride over float4)
// ---------------------------------------------------------------------------
__global__ void convert_kernel(const float* __restrict__ src, __half* __restrict__ dst,
                               int n4) {
    int i = blockIdx.x * blockDim.x + threadIdx.x;
    const int stride = gridDim.x * blockDim.x;
    for (; i < n4; i += stride) {
        float4 v = ((const float4*)src)[i];
        __half2 h0 = __floats2half2_rn(v.x, v.y);
        __half2 h1 = __floats2half2_rn(v.z, v.w);
        ((__half2*)dst)[2 * i + 0] = h0;
        ((__half2*)dst)[2 * i + 1] = h1;
    }
}

// ---------------------------------------------------------------------------
// Kernel 1: q_proj, grid (8 oc, 32 b): warp per output, 16 outputs per warp.
// ---------------------------------------------------------------------------
__global__ void qproj_kernel(const float* __restrict__ query,
                             const float* __restrict__ Wq,
                             const float* __restrict__ bq) {
    __shared__ float q_s[H_DIM];
    const int b = blockIdx.y;
    const int ob = blockIdx.x * 128;
    const int tid = threadIdx.x;
    for (int i = tid; i < H_DIM; i += 256) q_s[i] = query[b * H_DIM + i];
    __syncthreads();
    const int warp = tid >> 5, lane = tid & 31;
    for (int oi = 0; oi < 16; ++oi) {
        const int o = ob + warp * 16 + oi;
        const float* wrow = Wq + (size_t)o * H_DIM;
        float s = 0.f;
        #pragma unroll 8
        for (int h = lane; h < H_DIM; h += 32) s += q_s[h] * wrow[h];
        #pragma unroll
        for (int m = 16; m > 0; m >>= 1) s += __shfl_xor_sync(0xffffffffu, s, m);
        if (lane == 0) g_qproj[b * H_DIM + o] = s + bq[o];
    }
}

// ---------------------------------------------------------------------------
// Kernel 2: fused score GEMM, fp16 m16n8k16 mma.sync + ldmatrix.
// 3-stage cp.async pipeline, BK=64, ONE barrier per 64-wide K step.
// Block 128x128 per pass, 8 passes. 256 threads = 8 warps (4m x 2n),
// warp tile 32x64. fp32 accum.
// ---------------------------------------------------------------------------
#define BK       64
#define STAGES   3
#define NKT      (H_DIM / BK)                  // 16
#define LDPH     72                            // padded row stride (halves), 144B
#define ST_H     (128 * LDPH)                  // halves per tile (A or B)
#define OFF_AH   0
#define OFF_BH   (STAGES * ST_H)
#define HALVES   (2 * STAGES * ST_H)
#define OFF_QB   (HALVES / 2)                  // float index
#define OFF_VW   (OFF_QB + 128)
#define OFF_SC   (OFF_VW + 128)
#define SMEM_FLT (OFF_SC + 128)
#define SMEM_BYTES (SMEM_FLT * 4)              // 112128 B

__global__ void __launch_bounds__(256, 2) score_kernel(
    const float* __restrict__ bv,
    const float* __restrict__ Vw,
    const float* __restrict__ Vb) {

    extern __shared__ __align__(16) float smem[];
    __half* As = (__half*)smem + OFF_AH;      // [STAGES][128][72]
    __half* Bs = (__half*)smem + OFF_BH;
    float* qb_s = smem + OFF_QB;
    float* vw_s = smem + OFF_VW;
    float* score_s = smem + OFF_SC;

    const int tid = threadIdx.x;
    const int wid = tid >> 5, lane = tid & 31;
    const int warp_m = wid >> 1, warp_n = wid & 1;   // 4 x 2
    const int gid = lane >> 2, tig = lane & 3;
    const int l8 = lane & 7, sel = lane >> 3;

    const int r0 = blockIdx.x * 128;
    const int b  = r0 / T_DIM;
    const float* qp = g_qproj + b * H_DIM;

    if (tid < 128) score_s[tid] = 0.f;

    // Loader thread constants: 128 rows x 64 halves = 1024 chunks of 16B;
    // 256 threads x 4 iters. row = idx>>3, ch = idx&7.
    const int ld_row = tid >> 3;                 // base row (stride 32 rows/iter)
    const int ld_ch  = tid & 7;
    const uint32_t ld_soff = (uint32_t)(ld_row * LDPH + ld_ch * 8) * 2;  // bytes
    const uint32_t a_sbase = smem_u32(As) + ld_soff;
    const uint32_t b_sbase = smem_u32(Bs) + ld_soff;
    const __half* a_gbase = g_vals_h + (size_t)(r0 + ld_row) * H_DIM + ld_ch * 8;
    const size_t  g_row_step = (size_t)32 * H_DIM;      // 32 rows per iter

    // ldmatrix lane addressing (halves)
    const int a_row = warp_m * 32 + ((sel & 1) ? 8 : 0) + l8;
    const int a_kof = (sel & 2) ? 8 : 0;
    const int b_row = warp_n * 64 + ((sel & 2) ? 8 : 0) + l8;
    const int b_kof = (sel & 1) ? 8 : 0;
    const uint32_t a_lbase = smem_u32(As + a_row * LDPH + a_kof);
    const uint32_t b_lbase = smem_u32(Bs + b_row * LDPH + b_kof);
    const uint32_t stg_b = ST_H * 2;             // stage stride in bytes

    float sacc[4] = {0.f, 0.f, 0.f, 0.f};

    for (int oc = 0; oc < 8; ++oc) {
        const int ob = oc * 128;
        const __half* b_gbase = g_wv_h + (size_t)(ob + ld_row) * H_DIM + ld_ch * 8;
        __syncthreads();                 // prev pass fully done (epilogue + slots)
        if (tid < 128) {
            qb_s[tid] = qp[ob + tid] + bv[ob + tid];
            vw_s[tid] = Vw[ob + tid];
        }

        float c[2][8][4];
        #pragma unroll
        for (int mt = 0; mt < 2; ++mt)
            #pragma unroll
            for (int nt = 0; nt < 8; ++nt)
                #pragma unroll
                for (int i = 0; i < 4; ++i) c[mt][nt][i] = 0.f;

        // prologue: fill stages 0,1
        #pragma unroll
        for (int s = 0; s < STAGES - 1; ++s) {
            #pragma unroll
            for (int it = 0; it < 4; ++it) {
                cp_async16(a_sbase + s * stg_b + it * (32 * LDPH * 2),
                           a_gbase + s * BK + it * g_row_step);
                cp_async16(b_sbase + s * stg_b + it * (32 * LDPH * 2),
                           b_gbase + s * BK + it * g_row_step);
            }
            cp_commit();
        }

        int cur = 0, nxt = STAGES - 1;   // slot to fill holds tile kt+2
        for (int kt = 0; kt < NKT; ++kt) {
            cp_wait<STAGES - 2>();       // stage `cur` complete
            __syncthreads();             // slot `nxt` free (consumed at kt-1)

            // issue loads for tile kt+STAGES-1 FIRST (max latency cover)
            const int nk = kt + STAGES - 1;
            if (nk < NKT) {
                #pragma unroll
                for (int it = 0; it < 4; ++it) {
                    cp_async16(a_sbase + nxt * stg_b + it * (32 * LDPH * 2),
                               a_gbase + nk * BK + it * g_row_step);
                    cp_async16(b_sbase + nxt * stg_b + it * (32 * LDPH * 2),
                               b_gbase + nk * BK + it * g_row_step);
                }
            }
            cp_commit();

            const uint32_t a_base = a_lbase + cur * stg_b;
            const uint32_t b_base = b_lbase + cur * stg_b;

            #pragma unroll
            for (int ks = 0; ks < 4; ++ks) {                 // four k16 steps
                const uint32_t koff = ks * 32;               // 16 halves = 32B
                uint32_t af[2][4], bf[8][2];
                #pragma unroll
                for (int mt = 0; mt < 2; ++mt)
                    ldsm_x4(af[mt], a_base + mt * (16 * LDPH * 2) + koff);
                #pragma unroll
                for (int np = 0; np < 4; ++np) {
                    uint32_t r[4];
                    ldsm_x4(r, b_base + np * (16 * LDPH * 2) + koff);
                    bf[np * 2 + 0][0] = r[0];
                    bf[np * 2 + 0][1] = r[1];
                    bf[np * 2 + 1][0] = r[2];
                    bf[np * 2 + 1][1] = r[3];
                }
                #pragma unroll
                for (int mt = 0; mt < 2; ++mt)
                    #pragma unroll
                    for (int nt = 0; nt < 8; ++nt)
                        mma_f16(c[mt][nt], af[mt], bf[nt]);
            }

            cur = (cur == STAGES - 1) ? 0 : cur + 1;
            nxt = (nxt == STAGES - 1) ? 0 : nxt + 1;
        }

        // Epilogue: tanh + Vw contraction into per-lane row partials
        #pragma unroll
        for (int nt = 0; nt < 8; ++nt) {
            const int col0 = warp_n * 64 + nt * 8 + 2 * tig;
            const float vw0 = vw_s[col0],     qb0 = qb_s[col0];
            const float vw1 = vw_s[col0 + 1], qb1 = qb_s[col0 + 1];
            #pragma unroll
            for (int mt = 0; mt < 2; ++mt) {
                sacc[mt * 2 + 0] += vw0 * fast_tanh(c[mt][nt][0] + qb0)
                                  + vw1 * fast_tanh(c[mt][nt][1] + qb1);
                sacc[mt * 2 + 1] += vw0 * fast_tanh(c[mt][nt][2] + qb0)
                                  + vw1 * fast_tanh(c[mt][nt][3] + qb1);
            }
        }
    }

    #pragma unroll
    for (int i = 0; i < 4; ++i) {
        sacc[i] += __shfl_xor_sync(0xffffffffu, sacc[i], 1);
        sacc[i] += __shfl_xor_sync(0xffffffffu, sacc[i], 2);
    }
    if (tig == 0) {
        #pragma unroll
        for (int i = 0; i < 4; ++i) {
            const int row = warp_m * 32 + (i >> 1) * 16 + gid + (i & 1) * 8;
            atomicAdd(&score_s[row], sacc[i]);
        }
    }
    __syncthreads();
    if (tid < 128) g_score[r0 + tid] = score_s[tid] + Vb[0];
}

// ---------------------------------------------------------------------------
// Kernel 3: softmax over T per batch. Writes weights into d_out[B*H ..].
// ---------------------------------------------------------------------------
__global__ void softmax_kernel(float* __restrict__ d_out) {
    __shared__ float red[1024];
    const int b = blockIdx.x;
    const int tid = threadIdx.x;
    const float s0 = g_score[b * T_DIM + tid];
    const float s1 = g_score[b * T_DIM + 1024 + tid];
    red[tid] = fmaxf(s0, s1);
    __syncthreads();
    for (int s = 512; s > 0; s >>= 1) {
        if (tid < s) red[tid] = fmaxf(red[tid], red[tid + s]);
        __syncthreads();
    }
    const float mx = red[0];
    __syncthreads();
    const float e0 = expf(s0 - mx), e1 = expf(s1 - mx);
    red[tid] = e0 + e1;
    __syncthreads();
    for (int s = 512; s > 0; s >>= 1) {
        if (tid < s) red[tid] += red[tid + s];
        __syncthreads();
    }
    const float inv = 1.f / red[0];
    float* w = d_out + B_DIM * H_DIM + b * T_DIM;
    w[tid] = e0 * inv;
    w[tid + 1024] = e1 * inv;
}

// ---------------------------------------------------------------------------
// Kernel 4a: context partials over T chunks; 4b: deterministic reduce.
// ---------------------------------------------------------------------------
__global__ void __launch_bounds__(1024) ctx_partial_kernel(
    const float* __restrict__ values, const float* __restrict__ d_out_w) {
    __shared__ float w_s[256];
    const int ts = blockIdx.x, b = blockIdx.y;
    const int h = threadIdx.x;
    const float* w = d_out_w + b * T_DIM + ts * 256;
    if (h < 256) w_s[h] = w[h];
    __syncthreads();
    const float* vp = values + ((size_t)b * T_DIM + ts * 256) * H_DIM + h;
    float a0 = 0.f, a1 = 0.f, a2 = 0.f, a3 = 0.f;
    #pragma unroll 8
    for (int t = 0; t < 256; t += 4) {
        a0 += w_s[t + 0] * vp[(size_t)(t + 0) * H_DIM];
        a1 += w_s[t + 1] * vp[(size_t)(t + 1) * H_DIM];
        a2 += w_s[t + 2] * vp[(size_t)(t + 2) * H_DIM];
        a3 += w_s[t + 3] * vp[(size_t)(t + 3) * H_DIM];
    }
    g_ctx_part[(b * 8 + ts) * H_DIM + h] = (a0 + a1) + (a2 + a3);
}

__global__ void __launch_bounds__(1024) ctx_reduce_kernel(float* __restrict__ d_out) {
    const int b = blockIdx.x, h = threadIdx.x;
    float s = 0.f;
    #pragma unroll
    for (int ts = 0; ts < 8; ++ts) s += g_ctx_part[(b * 8 + ts) * H_DIM + h];
    d_out[b * H_DIM + h] = s;
}

// ---------------------------------------------------------------------------
extern "C" void kernel_launch(void* const* d_in, const int* in_sizes, int n_in,
                              void* d_out, int out_size) {
    const float* query  = (const float*)d_in[0];
    const float* values = (const float*)d_in[1];
    const float* Wq     = (const float*)d_in[2];
    const float* bq     = (const float*)d_in[3];
    const float* Wv     = (const float*)d_in[4];
    const float* bv     = (const float*)d_in[5];
    const float* Vw     = (const float*)d_in[6];
    const float* Vb     = (const float*)d_in[7];
    float* out = (float*)d_out;

    cudaFuncSetAttribute(score_kernel, cudaFuncAttributeMaxDynamicSharedMemorySize,
                         SMEM_BYTES);

    __half* vals_h;
    cudaGetSymbolAddress((void**)&vals_h, g_vals_h);
    __half* wv_h;
    cudaGetSymbolAddress((void**)&wv_h, g_wv_h);

    convert_kernel<<<8192, 256>>>(values, vals_h, (B_DIM * T_DIM * (H_DIM / 4)));
    convert_kernel<<<2048, 256>>>(Wv, wv_h, (H_DIM * H_DIM) / 4);
    qproj_kernel<<<dim3(8, B_DIM), 256>>>(query, Wq, bq);
    score_kernel<<<(B_DIM * T_DIM) / 128, 256, SMEM_BYTES>>>(bv, Vw, Vb);
    softmax_kernel<<<B_DIM, 1024>>>(out);
    ctx_partial_kernel<<<dim3(8, B_DIM), 1024>>>(values, out + B_DIM * H_DIM);
    ctx_reduce_kernel<<<B_DIM, 1024>>>(out);
}

// round 10
// speedup vs baseline: 2.1063x; 1.0113x over previous
#include <cuda_runtime.h>
#include <cuda_fp16.h>
#include <math.h>
#include <stdint.h>

#define B_DIM 32
#define T_DIM 2048
#define H_DIM 1024

// ---------------------------------------------------------------------------
// Scratch (allocation-free rule: __device__ globals)
// ---------------------------------------------------------------------------
__device__ float  g_qproj[B_DIM * H_DIM];
__device__ float  g_score[B_DIM * T_DIM];
__device__ float  g_ctx_part[B_DIM * 8 * H_DIM];
__device__ __half g_vals_h[(size_t)B_DIM * T_DIM * H_DIM];   // 128 MB
__device__ __half g_wv_h[H_DIM * H_DIM];

// ---------------------------------------------------------------------------
// PTX helpers (sm_80-compatible; tcgen05 is NOT available at compute_103)
// ---------------------------------------------------------------------------
__device__ __forceinline__ uint32_t smem_u32(const void* p) {
    uint32_t a;
    asm("{ .reg .u64 t; cvta.to.shared.u64 t, %1; cvt.u32.u64 %0, t; }" : "=r"(a) : "l"(p));
    return a;
}
__device__ __forceinline__ void cp_async16(uint32_t dst, const void* src) {
    asm volatile("cp.async.cg.shared.global [%0], [%1], 16;" :: "r"(dst), "l"(src));
}
__device__ __forceinline__ void cp_commit() {
    asm volatile("cp.async.commit_group;" ::: "memory");
}
template <int N>
__device__ __forceinline__ void cp_wait() {
    asm volatile("cp.async.wait_group %0;" :: "n"(N) : "memory");
}
__device__ __forceinline__ void ldsm_x4(uint32_t r[4], uint32_t addr) {
    asm volatile("ldmatrix.sync.aligned.m8n8.x4.shared.b16 {%0,%1,%2,%3}, [%4];"
                 : "=r"(r[0]), "=r"(r[1]), "=r"(r[2]), "=r"(r[3]) : "r"(addr));
}
__device__ __forceinline__ void mma_f16(float c[4], const uint32_t a[4], const uint32_t b[2]) {
    asm volatile(
        "mma.sync.aligned.m16n8k16.row.col.f32.f16.f16.f32 "
        "{%0,%1,%2,%3}, {%4,%5,%6,%7}, {%8,%9}, {%0,%1,%2,%3};"
        : "+f"(c[0]), "+f"(c[1]), "+f"(c[2]), "+f"(c[3])
        : "r"(a[0]), "r"(a[1]), "r"(a[2]), "r"(a[3]), "r"(b[0]), "r"(b[1]));
}
__device__ __forceinline__ float fast_tanh(float x) {
    float e = __expf(2.0f * x);
    return 1.0f - 2.0f / (e + 1.0f);
}

// ---------------------------------------------------------------------------
// Kernel 0: fp32 -> fp16 conversion (grid-stride over float4)
// ---------------------------------------------------------------------------
__global__ void convert_kernel(const float* __restrict__ src, __half* __restrict__ dst,
                               int n4) {
    int i = blockIdx.x * blockDim.x + threadIdx.x;
    const int stride = gridDim.x * blockDim.x;
    for (; i < n4; i += stride) {
        float4 v = ((const float4*)src)[i];
        __half2 h0 = __floats2half2_rn(v.x, v.y);
        __half2 h1 = __floats2half2_rn(v.z, v.w);
        ((__half2*)dst)[2 * i + 0] = h0;
        ((__half2*)dst)[2 * i + 1] = h1;
    }
}

// ---------------------------------------------------------------------------
// Kernel 1: q_proj, grid (8 oc, 32 b): warp per output, 16 outputs per warp.
// ---------------------------------------------------------------------------
__global__ void qproj_kernel(const float* __restrict__ query,
                             const float* __restrict__ Wq,
                             const float* __restrict__ bq) {
    __shared__ float q_s[H_DIM];
    const int b = blockIdx.y;
    const int ob = blockIdx.x * 128;
    const int tid = threadIdx.x;
    for (int i = tid; i < H_DIM; i += 256) q_s[i] = query[b * H_DIM + i];
    __syncthreads();
    const int warp = tid >> 5, lane = tid & 31;
    for (int oi = 0; oi < 16; ++oi) {
        const int o = ob + warp * 16 + oi;
        const float* wrow = Wq + (size_t)o * H_DIM;
        float s = 0.f;
        #pragma unroll 8
        for (int h = lane; h < H_DIM; h += 32) s += q_s[h] * wrow[h];
        #pragma unroll
        for (int m = 16; m > 0; m >>= 1) s += __shfl_xor_sync(0xffffffffu, s, m);
        if (lane == 0) g_qproj[b * H_DIM + o] = s + bq[o];
    }
}

// ---------------------------------------------------------------------------
// Kernel 2: fused score GEMM, fp16 m16n8k16 mma.sync + ldmatrix.
// 3-stage cp.async pipeline, BK=64. Per-warp K-step phase rotation breaks the
// post-barrier lockstep so ldsm (crossbar) and mma (tensor) phases of
// different warps overlap.
// Block 128x128 per pass, 8 passes. 256 threads = 8 warps (4m x 2n),
// warp tile 32x64. fp32 accum.
// ---------------------------------------------------------------------------
#define BK       64
#define STAGES   3
#define NKT      (H_DIM / BK)                  // 16
#define LDPH     72                            // padded row stride (halves), 144B
#define ST_H     (128 * LDPH)                  // halves per tile (A or B)
#define OFF_AH   0
#define OFF_BH   (STAGES * ST_H)
#define HALVES   (2 * STAGES * ST_H)
#define OFF_QB   (HALVES / 2)                  // float index
#define OFF_VW   (OFF_QB + 128)
#define OFF_SC   (OFF_VW + 128)
#define SMEM_FLT (OFF_SC + 128)
#define SMEM_BYTES (SMEM_FLT * 4)              // 112128 B

__global__ void __launch_bounds__(256, 2) score_kernel(
    const float* __restrict__ bv,
    const float* __restrict__ Vw,
    const float* __restrict__ Vb) {

    extern __shared__ __align__(16) float smem[];
    __half* As = (__half*)smem + OFF_AH;      // [STAGES][128][72]
    __half* Bs = (__half*)smem + OFF_BH;
    float* qb_s = smem + OFF_QB;
    float* vw_s = smem + OFF_VW;
    float* score_s = smem + OFF_SC;

    const int tid = threadIdx.x;
    const int wid = tid >> 5, lane = tid & 31;
    const int warp_m = wid >> 1, warp_n = wid & 1;   // 4 x 2
    const int gid = lane >> 2, tig = lane & 3;
    const int l8 = lane & 7, sel = lane >> 3;

    // Phase rotation: SMSP = wid&3 gets offset wid&3; the second warp on the
    // same SMSP (wid>=4) is pushed 2 further so SMSP-mates are anti-phased.
    const int ks0 = ((wid & 3) + ((wid >> 2) << 1)) & 3;

    const int r0 = blockIdx.x * 128;
    const int b  = r0 / T_DIM;
    const float* qp = g_qproj + b * H_DIM;

    if (tid < 128) score_s[tid] = 0.f;

    // Loader thread constants: 128 rows x 64 halves = 1024 chunks of 16B;
    // 256 threads x 4 iters. row = idx>>3, ch = idx&7.
    const int ld_row = tid >> 3;                 // base row (stride 32 rows/iter)
    const int ld_ch  = tid & 7;
    const uint32_t ld_soff = (uint32_t)(ld_row * LDPH + ld_ch * 8) * 2;  // bytes
    const uint32_t a_sbase = smem_u32(As) + ld_soff;
    const uint32_t b_sbase = smem_u32(Bs) + ld_soff;
    const __half* a_gbase = g_vals_h + (size_t)(r0 + ld_row) * H_DIM + ld_ch * 8;
    const size_t  g_row_step = (size_t)32 * H_DIM;      // 32 rows per iter

    // ldmatrix lane addressing (halves)
    const int a_row = warp_m * 32 + ((sel & 1) ? 8 : 0) + l8;
    const int a_kof = (sel & 2) ? 8 : 0;
    const int b_row = warp_n * 64 + ((sel & 2) ? 8 : 0) + l8;
    const int b_kof = (sel & 1) ? 8 : 0;
    const uint32_t a_lbase = smem_u32(As + a_row * LDPH + a_kof);
    const uint32_t b_lbase = smem_u32(Bs + b_row * LDPH + b_kof);
    const uint32_t stg_b = ST_H * 2;             // stage stride in bytes

    float sacc[4] = {0.f, 0.f, 0.f, 0.f};

    for (int oc = 0; oc < 8; ++oc) {
        const int ob = oc * 128;
        const __half* b_gbase = g_wv_h + (size_t)(ob + ld_row) * H_DIM + ld_ch * 8;
        __syncthreads();                 // prev pass fully done (epilogue + slots)
        if (tid < 128) {
            qb_s[tid] = qp[ob + tid] + bv[ob + tid];
            vw_s[tid] = Vw[ob + tid];
        }

        float c[2][8][4];
        #pragma unroll
        for (int mt = 0; mt < 2; ++mt)
            #pragma unroll
            for (int nt = 0; nt < 8; ++nt)
                #pragma unroll
                for (int i = 0; i < 4; ++i) c[mt][nt][i] = 0.f;

        // prologue: fill stages 0,1
        #pragma unroll
        for (int s = 0; s < STAGES - 1; ++s) {
            #pragma unroll
            for (int it = 0; it < 4; ++it) {
                cp_async16(a_sbase + s * stg_b + it * (32 * LDPH * 2),
                           a_gbase + s * BK + it * g_row_step);
                cp_async16(b_sbase + s * stg_b + it * (32 * LDPH * 2),
                           b_gbase + s * BK + it * g_row_step);
            }
            cp_commit();
        }

        int cur = 0, nxt = STAGES - 1;
        for (int kt = 0; kt < NKT; ++kt) {
            cp_wait<STAGES - 2>();       // stage `cur` complete
            __syncthreads();             // slot `nxt` free (consumed at kt-1)

            // issue loads for tile kt+STAGES-1 FIRST (max latency cover)
            const int nk = kt + STAGES - 1;
            if (nk < NKT) {
                #pragma unroll
                for (int it = 0; it < 4; ++it) {
                    cp_async16(a_sbase + nxt * stg_b + it * (32 * LDPH * 2),
                               a_gbase + nk * BK + it * g_row_step);
                    cp_async16(b_sbase + nxt * stg_b + it * (32 * LDPH * 2),
                               b_gbase + nk * BK + it * g_row_step);
                }
            }
            cp_commit();

            const uint32_t a_base = a_lbase + cur * stg_b;
            const uint32_t b_base = b_lbase + cur * stg_b;

            #pragma unroll
            for (int kss = 0; kss < 4; ++kss) {              // four k16 steps
                const int ks = (kss + ks0) & 3;              // per-warp rotation
                const uint32_t koff = (uint32_t)ks * 32;     // 16 halves = 32B
                uint32_t af[2][4], bf[8][2];
                #pragma unroll
                for (int mt = 0; mt < 2; ++mt)
                    ldsm_x4(af[mt], a_base + mt * (16 * LDPH * 2) + koff);
                #pragma unroll
                for (int np = 0; np < 4; ++np) {
                    uint32_t r[4];
                    ldsm_x4(r, b_base + np * (16 * LDPH * 2) + koff);
                    bf[np * 2 + 0][0] = r[0];
                    bf[np * 2 + 0][1] = r[1];
                    bf[np * 2 + 1][0] = r[2];
                    bf[np * 2 + 1][1] = r[3];
                }
                #pragma unroll
                for (int mt = 0; mt < 2; ++mt)
                    #pragma unroll
                    for (int nt = 0; nt < 8; ++nt)
                        mma_f16(c[mt][nt], af[mt], bf[nt]);
            }

            cur = (cur == STAGES - 1) ? 0 : cur + 1;
            nxt = (nxt == STAGES - 1) ? 0 : nxt + 1;
        }

        // Epilogue: tanh + Vw contraction into per-lane row partials
        #pragma unroll
        for (int nt = 0; nt < 8; ++nt) {
            const int col0 = warp_n * 64 + nt * 8 + 2 * tig;
            const float vw0 = vw_s[col0],     qb0 = qb_s[col0];
            const float vw1 = vw_s[col0 + 1], qb1 = qb_s[col0 + 1];
            #pragma unroll
            for (int mt = 0; mt < 2; ++mt) {
                sacc[mt * 2 + 0] += vw0 * fast_tanh(c[mt][nt][0] + qb0)
                                  + vw1 * fast_tanh(c[mt][nt][1] + qb1);
                sacc[mt * 2 + 1] += vw0 * fast_tanh(c[mt][nt][2] + qb0)
                                  + vw1 * fast_tanh(c[mt][nt][3] + qb1);
            }
        }
    }

    #pragma unroll
    for (int i = 0; i < 4; ++i) {
        sacc[i] += __shfl_xor_sync(0xffffffffu, sacc[i], 1);
        sacc[i] += __shfl_xor_sync(0xffffffffu, sacc[i], 2);
    }
    if (tig == 0) {
        #pragma unroll
        for (int i = 0; i < 4; ++i) {
            const int row = warp_m * 32 + (i >> 1) * 16 + gid + (i & 1) * 8;
            atomicAdd(&score_s[row], sacc[i]);
        }
    }
    __syncthreads();
    if (tid < 128) g_score[r0 + tid] = score_s[tid] + Vb[0];
}

// ---------------------------------------------------------------------------
// Kernel 3: softmax over T per batch. Writes weights into d_out[B*H ..].
// ---------------------------------------------------------------------------
__global__ void softmax_kernel(float* __restrict__ d_out) {
    __shared__ float red[1024];
    const int b = blockIdx.x;
    const int tid = threadIdx.x;
    const float s0 = g_score[b * T_DIM + tid];
    const float s1 = g_score[b * T_DIM + 1024 + tid];
    red[tid] = fmaxf(s0, s1);
    __syncthreads();
    for (int s = 512; s > 0; s >>= 1) {
        if (tid < s) red[tid] = fmaxf(red[tid], red[tid + s]);
        __syncthreads();
    }
    const float mx = red[0];
    __syncthreads();
    const float e0 = expf(s0 - mx), e1 = expf(s1 - mx);
    red[tid] = e0 + e1;
    __syncthreads();
    for (int s = 512; s > 0; s >>= 1) {
        if (tid < s) red[tid] += red[tid + s];
        __syncthreads();
    }
    const float inv = 1.f / red[0];
    float* w = d_out + B_DIM * H_DIM + b * T_DIM;
    w[tid] = e0 * inv;
    w[tid + 1024] = e1 * inv;
}

// ---------------------------------------------------------------------------
// Kernel 4a: context partials over T chunks; 4b: deterministic reduce.
// ---------------------------------------------------------------------------
__global__ void __launch_bounds__(1024) ctx_partial_kernel(
    const float* __restrict__ values, const float* __restrict__ d_out_w) {
    __shared__ float w_s[256];
    const int ts = blockIdx.x, b = blockIdx.y;
    const int h = threadIdx.x;
    const float* w = d_out_w + b * T_DIM + ts * 256;
    if (h < 256) w_s[h] = w[h];
    __syncthreads();
    const float* vp = values + ((size_t)b * T_DIM + ts * 256) * H_DIM + h;
    float a0 = 0.f, a1 = 0.f, a2 = 0.f, a3 = 0.f;
    #pragma unroll 8
    for (int t = 0; t < 256; t += 4) {
        a0 += w_s[t + 0] * vp[(size_t)(t + 0) * H_DIM];
        a1 += w_s[t + 1] * vp[(size_t)(t + 1) * H_DIM];
        a2 += w_s[t + 2] * vp[(size_t)(t + 2) * H_DIM];
        a3 += w_s[t + 3] * vp[(size_t)(t + 3) * H_DIM];
    }
    g_ctx_part[(b * 8 + ts) * H_DIM + h] = (a0 + a1) + (a2 + a3);
}

__global__ void __launch_bounds__(1024) ctx_reduce_kernel(float* __restrict__ d_out) {
    const int b = blockIdx.x, h = threadIdx.x;
    float s = 0.f;
    #pragma unroll
    for (int ts = 0; ts < 8; ++ts) s += g_ctx_part[(b * 8 + ts) * H_DIM + h];
    d_out[b * H_DIM + h] = s;
}

// ---------------------------------------------------------------------------
extern "C" void kernel_launch(void* const* d_in, const int* in_sizes, int n_in,
                              void* d_out, int out_size) {
    const float* query  = (const float*)d_in[0];
    const float* values = (const float*)d_in[1];
    const float* Wq     = (const float*)d_in[2];
    const float* bq     = (const float*)d_in[3];
    const float* Wv     = (const float*)d_in[4];
    const float* bv     = (const float*)d_in[5];
    const float* Vw     = (const float*)d_in[6];
    const float* Vb     = (const float*)d_in[7];
    float* out = (float*)d_out;

    cudaFuncSetAttribute(score_kernel, cudaFuncAttributeMaxDynamicSharedMemorySize,
                         SMEM_BYTES);

    __half* vals_h;
    cudaGetSymbolAddress((void**)&vals_h, g_vals_h);
    __half* wv_h;
    cudaGetSymbolAddress((void**)&wv_h, g_wv_h);

    convert_kernel<<<8192, 256>>>(values, vals_h, (B_DIM * T_DIM * (H_DIM / 4)));
    convert_kernel<<<2048, 256>>>(Wv, wv_h, (H_DIM * H_DIM) / 4);
    qproj_kernel<<<dim3(8, B_DIM), 256>>>(query, Wq, bq);
    score_kernel<<<(B_DIM * T_DIM) / 128, 256, SMEM_BYTES>>>(bv, Vw, Vb);
    softmax_kernel<<<B_DIM, 1024>>>(out);
    ctx_partial_kernel<<<dim3(8, B_DIM), 1024>>>(values, out + B_DIM * H_DIM);
    ctx_reduce_kernel<<<B_DIM, 1024>>>(out);
}

// round 11
// speedup vs baseline: 2.2968x; 1.0905x over previous
#include <cuda_runtime.h>
#include <cuda_fp16.h>
#include <math.h>
#include <stdint.h>

#define B_DIM 32
#define T_DIM 2048
#define H_DIM 1024
#define OCG   4                                 // oc groups (CTAs per row-block)

// ---------------------------------------------------------------------------
// Scratch (allocation-free rule: __device__ globals)
// ---------------------------------------------------------------------------
__device__ float  g_qproj[B_DIM * H_DIM];
__device__ float  g_score_part[OCG * B_DIM * T_DIM];
__device__ float  g_ctx_part[B_DIM * 8 * H_DIM];
__device__ __half g_vals_h[(size_t)B_DIM * T_DIM * H_DIM];   // 128 MB
__device__ __half g_wv_h[H_DIM * H_DIM];

// ---------------------------------------------------------------------------
// PTX helpers (sm_80-compatible; tcgen05 is NOT available at compute_103)
// ---------------------------------------------------------------------------
__device__ __forceinline__ uint32_t smem_u32(const void* p) {
    uint32_t a;
    asm("{ .reg .u64 t; cvta.to.shared.u64 t, %1; cvt.u32.u64 %0, t; }" : "=r"(a) : "l"(p));
    return a;
}
__device__ __forceinline__ void cp_async16(uint32_t dst, const void* src) {
    asm volatile("cp.async.cg.shared.global [%0], [%1], 16;" :: "r"(dst), "l"(src));
}
__device__ __forceinline__ void cp_commit() {
    asm volatile("cp.async.commit_group;" ::: "memory");
}
template <int N>
__device__ __forceinline__ void cp_wait() {
    asm volatile("cp.async.wait_group %0;" :: "n"(N) : "memory");
}
__device__ __forceinline__ void ldsm_x4(uint32_t r[4], uint32_t addr) {
    asm volatile("ldmatrix.sync.aligned.m8n8.x4.shared.b16 {%0,%1,%2,%3}, [%4];"
                 : "=r"(r[0]), "=r"(r[1]), "=r"(r[2]), "=r"(r[3]) : "r"(addr));
}
__device__ __forceinline__ void mma_f16(float c[4], const uint32_t a[4], const uint32_t b[2]) {
    asm volatile(
        "mma.sync.aligned.m16n8k16.row.col.f32.f16.f16.f32 "
        "{%0,%1,%2,%3}, {%4,%5,%6,%7}, {%8,%9}, {%0,%1,%2,%3};"
        : "+f"(c[0]), "+f"(c[1]), "+f"(c[2]), "+f"(c[3])
        : "r"(a[0]), "r"(a[1]), "r"(a[2]), "r"(a[3]), "r"(b[0]), "r"(b[1]));
}
__device__ __forceinline__ float fast_tanh(float x) {
    float e = __expf(2.0f * x);
    return 1.0f - 2.0f / (e + 1.0f);
}

// ---------------------------------------------------------------------------
// Kernel 0: fp32 -> fp16 conversion (grid-stride over float4)
// ---------------------------------------------------------------------------
__global__ void convert_kernel(const float* __restrict__ src, __half* __restrict__ dst,
                               int n4) {
    int i = blockIdx.x * blockDim.x + threadIdx.x;
    const int stride = gridDim.x * blockDim.x;
    for (; i < n4; i += stride) {
        float4 v = ((const float4*)src)[i];
        __half2 h0 = __floats2half2_rn(v.x, v.y);
        __half2 h1 = __floats2half2_rn(v.z, v.w);
        ((__half2*)dst)[2 * i + 0] = h0;
        ((__half2*)dst)[2 * i + 1] = h1;
    }
}

// ---------------------------------------------------------------------------
// Kernel 1: q_proj, grid (8 oc, 32 b): warp per output, 16 outputs per warp.
// ---------------------------------------------------------------------------
__global__ void qproj_kernel(const float* __restrict__ query,
                             const float* __restrict__ Wq,
                             const float* __restrict__ bq) {
    __shared__ float q_s[H_DIM];
    const int b = blockIdx.y;
    const int ob = blockIdx.x * 128;
    const int tid = threadIdx.x;
    for (int i = tid; i < H_DIM; i += 256) q_s[i] = query[b * H_DIM + i];
    __syncthreads();
    const int warp = tid >> 5, lane = tid & 31;
    for (int oi = 0; oi < 16; ++oi) {
        const int o = ob + warp * 16 + oi;
        const float* wrow = Wq + (size_t)o * H_DIM;
        float s = 0.f;
        #pragma unroll 8
        for (int h = lane; h < H_DIM; h += 32) s += q_s[h] * wrow[h];
        #pragma unroll
        for (int m = 16; m > 0; m >>= 1) s += __shfl_xor_sync(0xffffffffu, s, m);
        if (lane == 0) g_qproj[b * H_DIM + o] = s + bq[o];
    }
}

// ---------------------------------------------------------------------------
// Kernel 2: fused score GEMM, fp16 m16n8k16 mma.sync + ldmatrix.
// Grid (512 row-blocks, OCG oc-groups); each CTA does 8/OCG o-chunk passes and
// writes a partial score (summed deterministically in softmax). Finer grain
// kills the 1.73-wave quantization tail.
// 3-stage cp.async, BK=64, per-warp K-step phase rotation.
// 256 threads = 8 warps (4m x 2n), warp tile 32x64, fp32 accum.
// ---------------------------------------------------------------------------
#define BK       64
#define STAGES   3
#define NKT      (H_DIM / BK)                  // 16
#define LDPH     72                            // padded row stride (halves), 144B
#define ST_H     (128 * LDPH)                  // halves per tile (A or B)
#define OFF_AH   0
#define OFF_BH   (STAGES * ST_H)
#define HALVES   (2 * STAGES * ST_H)
#define OFF_QB   (HALVES / 2)                  // float index
#define OFF_VW   (OFF_QB + 128)
#define OFF_SC   (OFF_VW + 128)
#define SMEM_FLT (OFF_SC + 128)
#define SMEM_BYTES (SMEM_FLT * 4)              // 112128 B
#define OC_PER   (8 / OCG)                     // passes per CTA

__global__ void __launch_bounds__(256, 2) score_kernel(
    const float* __restrict__ bv,
    const float* __restrict__ Vw) {

    extern __shared__ __align__(16) float smem[];
    __half* As = (__half*)smem + OFF_AH;      // [STAGES][128][72]
    __half* Bs = (__half*)smem + OFF_BH;
    float* qb_s = smem + OFF_QB;
    float* vw_s = smem + OFF_VW;
    float* score_s = smem + OFF_SC;

    const int tid = threadIdx.x;
    const int wid = tid >> 5, lane = tid & 31;
    const int warp_m = wid >> 1, warp_n = wid & 1;   // 4 x 2
    const int gid = lane >> 2, tig = lane & 3;
    const int l8 = lane & 7, sel = lane >> 3;

    // Per-warp K-step phase rotation (de-lockstep)
    const int ks0 = ((wid & 3) + ((wid >> 2) << 1)) & 3;

    const int r0 = blockIdx.x * 128;
    const int grp = blockIdx.y;                  // oc group
    const int b  = r0 / T_DIM;
    const float* qp = g_qproj + b * H_DIM;

    if (tid < 128) score_s[tid] = 0.f;

    // Loader thread constants
    const int ld_row = tid >> 3;
    const int ld_ch  = tid & 7;
    const uint32_t ld_soff = (uint32_t)(ld_row * LDPH + ld_ch * 8) * 2;  // bytes
    const uint32_t a_sbase = smem_u32(As) + ld_soff;
    const uint32_t b_sbase = smem_u32(Bs) + ld_soff;
    const __half* a_gbase = g_vals_h + (size_t)(r0 + ld_row) * H_DIM + ld_ch * 8;
    const size_t  g_row_step = (size_t)32 * H_DIM;

    // ldmatrix lane addressing (halves)
    const int a_row = warp_m * 32 + ((sel & 1) ? 8 : 0) + l8;
    const int a_kof = (sel & 2) ? 8 : 0;
    const int b_row = warp_n * 64 + ((sel & 2) ? 8 : 0) + l8;
    const int b_kof = (sel & 1) ? 8 : 0;
    const uint32_t a_lbase = smem_u32(As + a_row * LDPH + a_kof);
    const uint32_t b_lbase = smem_u32(Bs + b_row * LDPH + b_kof);
    const uint32_t stg_b = ST_H * 2;

    float sacc[4] = {0.f, 0.f, 0.f, 0.f};

    for (int oc = grp * OC_PER; oc < grp * OC_PER + OC_PER; ++oc) {
        const int ob = oc * 128;
        const __half* b_gbase = g_wv_h + (size_t)(ob + ld_row) * H_DIM + ld_ch * 8;
        __syncthreads();                 // prev pass fully done (epilogue + slots)
        if (tid < 128) {
            qb_s[tid] = qp[ob + tid] + bv[ob + tid];
            vw_s[tid] = Vw[ob + tid];
        }

        float c[2][8][4];
        #pragma unroll
        for (int mt = 0; mt < 2; ++mt)
            #pragma unroll
            for (int nt = 0; nt < 8; ++nt)
                #pragma unroll
                for (int i = 0; i < 4; ++i) c[mt][nt][i] = 0.f;

        // prologue: fill stages 0,1
        #pragma unroll
        for (int s = 0; s < STAGES - 1; ++s) {
            #pragma unroll
            for (int it = 0; it < 4; ++it) {
                cp_async16(a_sbase + s * stg_b + it * (32 * LDPH * 2),
                           a_gbase + s * BK + it * g_row_step);
                cp_async16(b_sbase + s * stg_b + it * (32 * LDPH * 2),
                           b_gbase + s * BK + it * g_row_step);
            }
            cp_commit();
        }

        int cur = 0, nxt = STAGES - 1;
        for (int kt = 0; kt < NKT; ++kt) {
            cp_wait<STAGES - 2>();       // stage `cur` complete
            __syncthreads();             // slot `nxt` free (consumed at kt-1)

            const int nk = kt + STAGES - 1;
            if (nk < NKT) {
                #pragma unroll
                for (int it = 0; it < 4; ++it) {
                    cp_async16(a_sbase + nxt * stg_b + it * (32 * LDPH * 2),
                               a_gbase + nk * BK + it * g_row_step);
                    cp_async16(b_sbase + nxt * stg_b + it * (32 * LDPH * 2),
                               b_gbase + nk * BK + it * g_row_step);
                }
            }
            cp_commit();

            const uint32_t a_base = a_lbase + cur * stg_b;
            const uint32_t b_base = b_lbase + cur * stg_b;

            #pragma unroll
            for (int kss = 0; kss < 4; ++kss) {
                const int ks = (kss + ks0) & 3;
                const uint32_t koff = (uint32_t)ks * 32;
                uint32_t af[2][4], bf[8][2];
                #pragma unroll
                for (int mt = 0; mt < 2; ++mt)
                    ldsm_x4(af[mt], a_base + mt * (16 * LDPH * 2) + koff);
                #pragma unroll
                for (int np = 0; np < 4; ++np) {
                    uint32_t r[4];
                    ldsm_x4(r, b_base + np * (16 * LDPH * 2) + koff);
                    bf[np * 2 + 0][0] = r[0];
                    bf[np * 2 + 0][1] = r[1];
                    bf[np * 2 + 1][0] = r[2];
                    bf[np * 2 + 1][1] = r[3];
                }
                #pragma unroll
                for (int mt = 0; mt < 2; ++mt)
                    #pragma unroll
                    for (int nt = 0; nt < 8; ++nt)
                        mma_f16(c[mt][nt], af[mt], bf[nt]);
            }

            cur = (cur == STAGES - 1) ? 0 : cur + 1;
            nxt = (nxt == STAGES - 1) ? 0 : nxt + 1;
        }

        // Epilogue: tanh + Vw contraction into per-lane row partials
        #pragma unroll
        for (int nt = 0; nt < 8; ++nt) {
            const int col0 = warp_n * 64 + nt * 8 + 2 * tig;
            const float vw0 = vw_s[col0],     qb0 = qb_s[col0];
            const float vw1 = vw_s[col0 + 1], qb1 = qb_s[col0 + 1];
            #pragma unroll
            for (int mt = 0; mt < 2; ++mt) {
                sacc[mt * 2 + 0] += vw0 * fast_tanh(c[mt][nt][0] + qb0)
                                  + vw1 * fast_tanh(c[mt][nt][1] + qb1);
                sacc[mt * 2 + 1] += vw0 * fast_tanh(c[mt][nt][2] + qb0)
                                  + vw1 * fast_tanh(c[mt][nt][3] + qb1);
            }
        }
    }

    #pragma unroll
    for (int i = 0; i < 4; ++i) {
        sacc[i] += __shfl_xor_sync(0xffffffffu, sacc[i], 1);
        sacc[i] += __shfl_xor_sync(0xffffffffu, sacc[i], 2);
    }
    if (tig == 0) {
        #pragma unroll
        for (int i = 0; i < 4; ++i) {
            const int row = warp_m * 32 + (i >> 1) * 16 + gid + (i & 1) * 8;
            atomicAdd(&score_s[row], sacc[i]);
        }
    }
    __syncthreads();
    if (tid < 128) g_score_part[grp * (B_DIM * T_DIM) + r0 + tid] = score_s[tid];
}

// ---------------------------------------------------------------------------
// Kernel 3: softmax over T per batch (sums the OCG partials deterministically;
// Vb omitted — constant shift is a softmax no-op and raw scores aren't output).
// ---------------------------------------------------------------------------
__global__ void softmax_kernel(float* __restrict__ d_out) {
    __shared__ float red[1024];
    const int b = blockIdx.x;
    const int tid = threadIdx.x;
    const int i0 = b * T_DIM + tid;
    const int i1 = b * T_DIM + 1024 + tid;
    float s0 = 0.f, s1 = 0.f;
    #pragma unroll
    for (int g = 0; g < OCG; ++g) {
        s0 += g_score_part[g * (B_DIM * T_DIM) + i0];
        s1 += g_score_part[g * (B_DIM * T_DIM) + i1];
    }
    red[tid] = fmaxf(s0, s1);
    __syncthreads();
    for (int s = 512; s > 0; s >>= 1) {
        if (tid < s) red[tid] = fmaxf(red[tid], red[tid + s]);
        __syncthreads();
    }
    const float mx = red[0];
    __syncthreads();
    const float e0 = expf(s0 - mx), e1 = expf(s1 - mx);
    red[tid] = e0 + e1;
    __syncthreads();
    for (int s = 512; s > 0; s >>= 1) {
        if (tid < s) red[tid] += red[tid + s];
        __syncthreads();
    }
    const float inv = 1.f / red[0];
    float* w = d_out + B_DIM * H_DIM + b * T_DIM;
    w[tid] = e0 * inv;
    w[tid + 1024] = e1 * inv;
}

// ---------------------------------------------------------------------------
// Kernel 4a: context partials over T chunks; 4b: deterministic reduce.
// ---------------------------------------------------------------------------
__global__ void __launch_bounds__(1024) ctx_partial_kernel(
    const float* __restrict__ values, const float* __restrict__ d_out_w) {
    __shared__ float w_s[256];
    const int ts = blockIdx.x, b = blockIdx.y;
    const int h = threadIdx.x;
    const float* w = d_out_w + b * T_DIM + ts * 256;
    if (h < 256) w_s[h] = w[h];
    __syncthreads();
    const float* vp = values + ((size_t)b * T_DIM + ts * 256) * H_DIM + h;
    float a0 = 0.f, a1 = 0.f, a2 = 0.f, a3 = 0.f;
    #pragma unroll 8
    for (int t = 0; t < 256; t += 4) {
        a0 += w_s[t + 0] * vp[(size_t)(t + 0) * H_DIM];
        a1 += w_s[t + 1] * vp[(size_t)(t + 1) * H_DIM];
        a2 += w_s[t + 2] * vp[(size_t)(t + 2) * H_DIM];
        a3 += w_s[t + 3] * vp[(size_t)(t + 3) * H_DIM];
    }
    g_ctx_part[(b * 8 + ts) * H_DIM + h] = (a0 + a1) + (a2 + a3);
}

__global__ void __launch_bounds__(1024) ctx_reduce_kernel(float* __restrict__ d_out) {
    const int b = blockIdx.x, h = threadIdx.x;
    float s = 0.f;
    #pragma unroll
    for (int ts = 0; ts < 8; ++ts) s += g_ctx_part[(b * 8 + ts) * H_DIM + h];
    d_out[b * H_DIM + h] = s;
}

// ---------------------------------------------------------------------------
extern "C" void kernel_launch(void* const* d_in, const int* in_sizes, int n_in,
                              void* d_out, int out_size) {
    const float* query  = (const float*)d_in[0];
    const float* values = (const float*)d_in[1];
    const float* Wq     = (const float*)d_in[2];
    const float* bq     = (const float*)d_in[3];
    const float* Wv     = (const float*)d_in[4];
    const float* bv     = (const float*)d_in[5];
    const float* Vw     = (const float*)d_in[6];
    float* out = (float*)d_out;

    cudaFuncSetAttribute(score_kernel, cudaFuncAttributeMaxDynamicSharedMemorySize,
                         SMEM_BYTES);

    __half* vals_h;
    cudaGetSymbolAddress((void**)&vals_h, g_vals_h);
    __half* wv_h;
    cudaGetSymbolAddress((void**)&wv_h, g_wv_h);

    convert_kernel<<<8192, 256>>>(values, vals_h, (B_DIM * T_DIM * (H_DIM / 4)));
    convert_kernel<<<2048, 256>>>(Wv, wv_h, (H_DIM * H_DIM) / 4);
    qproj_kernel<<<dim3(8, B_DIM), 256>>>(query, Wq, bq);
    score_kernel<<<dim3((B_DIM * T_DIM) / 128, OCG), 256, SMEM_BYTES>>>(bv, Vw);
    softmax_kernel<<<B_DIM, 1024>>>(out);
    ctx_partial_kernel<<<dim3(8, B_DIM), 1024>>>(values, out + B_DIM * H_DIM);
    ctx_reduce_kernel<<<B_DIM, 1024>>>(out);
}